// round 2
// baseline (speedup 1.0000x reference)
#include <cuda_runtime.h>
#include <math.h>

#define NB 128
#define NQ 30
#define ND 256
#define NE 300
#define XP 304
#define NSTEP 19   // ceil(300/16); 19*16 = 304 = XP

typedef unsigned long long u64;

#define FMA2(acc, a, b) asm("fma.rn.f32x2 %0, %1, %2, %0;" : "+l"(acc) : "l"(a), "l"(b))

__device__ __forceinline__ float2 unpack2(u64 v) {
    float2 r;
    asm("mov.b64 {%0, %1}, %2;" : "=f"(r.x), "=f"(r.y) : "l"(v));
    return r;
}

// ---------------- scratch ----------------
__device__ float g_WT[230400];            // stacked transposed weights [k][c] per gram
__device__ float g_Xq[NB * 32 * XP];      // padded query embeddings
__device__ float g_Xd[NB * ND * XP];      // padded doc embeddings
__device__ float g_Q[NB * NQ * 384];      // normalized query conv outputs
__device__ float g_D[NB * ND * 384];      // normalized doc conv outputs
__device__ float g_feat[NB * 99];

// ---------------- weight transpose/stack ----------------
__global__ __launch_bounds__(256) void prep_wt(const float* __restrict__ w1,
                                               const float* __restrict__ w2,
                                               const float* __restrict__ w3)
{
    int idx = blockIdx.x * 256 + threadIdx.x;
    if (idx >= 230400) return;
    int g, off;
    if (idx < 38400)       { g = 0; off = idx; }
    else if (idx < 115200) { g = 1; off = idx - 38400; }
    else                   { g = 2; off = idx - 115200; }
    int k = off >> 7;
    int c = off & 127;
    int tap = k / 300;
    int e = k - tap * 300;
    const float* w = (g == 0) ? w1 : ((g == 1) ? w2 : w3);
    g_WT[idx] = w[(c * 300 + e) * (g + 1) + tap];
}

// ---------------- X padding (row stride 304, 16B aligned, zero pad cols) ----------------
__global__ __launch_bounds__(256) void prep_xd(const float* __restrict__ X)
{
    int idx = blockIdx.x * 256 + threadIdx.x;
    const int T = NB * ND * (XP / 4);
    if (idx >= T) return;
    int e4 = idx % 76;
    int row = idx / 76;
    int e = e4 * 4;
    float4 v = make_float4(0.f, 0.f, 0.f, 0.f);
    if (e < NE) {
        const float* s = X + (size_t)row * NE + e;
        v = make_float4(s[0], s[1], s[2], s[3]);
    }
    *(float4*)&g_Xd[(size_t)row * XP + e] = v;
}

__global__ __launch_bounds__(256) void prep_xq(const float* __restrict__ X)
{
    int idx = blockIdx.x * 256 + threadIdx.x;
    const int T = NB * 32 * (XP / 4);
    if (idx >= T) return;
    int e4 = idx % 76;
    int row = idx / 76;
    int b = row >> 5, p = row & 31;
    int e = e4 * 4;
    float4 v = make_float4(0.f, 0.f, 0.f, 0.f);
    if (e < NE && p < NQ) {
        const float* s = X + ((size_t)(b * NQ + p)) * NE + e;
        v = make_float4(s[0], s[1], s[2], s[3]);
    }
    *(float4*)&g_Xq[(size_t)row * XP + e] = v;
}

// ---------------- conv + bias + relu + L2 normalize (FFMA2 GEMM) ----------------
// GEMM per (b, g, M-tile): C[TM,128] = sum_tap A_shift[TM, 300] x W_tap[300, 128]
// K paired: acc u64 holds (even-k sum, odd-k sum); final C = lo + hi.
// As[p][kk]  (TM x 16, kk-contiguous -> LDS.64 gives a k-pair)
// Bs[kk2][c][2] (pair-interleaved -> LDS.128 gives two c's worth of k-pairs)
template<int TM, int MR, int L, int XR, bool IS_Q>
__global__ __launch_bounds__(256, 2) void conv2(const float* __restrict__ bs0,
                                                const float* __restrict__ bs1,
                                                const float* __restrict__ bs2)
{
    __shared__ float As[TM * 16];
    __shared__ float Bs[8 * 256];

    const int g  = blockIdx.z;
    const int b  = blockIdx.y;
    const int p0 = blockIdx.x * TM;
    const float* WT   = g_WT + ((g == 0) ? 0 : ((g == 1) ? 38400 : 115200));
    const float* bias = (g == 0) ? bs0 : ((g == 1) ? bs1 : bs2);
    const float* Xp   = IS_Q ? g_Xq : g_Xd;
    float* OUT        = IS_Q ? g_Q  : g_D;

    const int tid = threadIdx.x;
    const int ty = tid >> 4, tx = tid & 15;
    const int m0 = ty * MR, n0 = tx * 8;
    const float* Xb = Xp + (size_t)b * XR * XP;

    const int S = (g + 1) * NSTEP;

    // loader lane roles
    const int pA  = tid >> 2;          // row within tile (A loader)
    const int e4  = (tid & 3) * 4;     // kk offset (A loader)
    const int kk2B = tid >> 5;         // k-pair row (B loader)
    const int c0B  = (tid & 31) * 4;   // channel base (B loader)

    u64 acc[MR][8];
#pragma unroll
    for (int i = 0; i < MR; i++)
#pragma unroll
        for (int j = 0; j < 8; j++) acc[i][j] = 0ull;

    auto doLoad = [&](int s, float4& A, float4& B0, float4& B1) {
        int tap = s / NSTEP;
        int ks = (s - tap * NSTEP) * 16;
        A = make_float4(0.f, 0.f, 0.f, 0.f);
        if (TM * 4 >= 256 || tid < TM * 4) {
            int pos = p0 + pA + tap;
            if (pos < L) A = *(const float4*)&Xb[(size_t)pos * XP + ks + e4];
        }
        int e0 = ks + 2 * kk2B;
        const float* wr = WT + ((size_t)(tap * 300 + e0)) * 128 + c0B;
        B0 = (e0     < NE) ? *(const float4*)wr         : make_float4(0.f, 0.f, 0.f, 0.f);
        B1 = (e0 + 1 < NE) ? *(const float4*)(wr + 128) : make_float4(0.f, 0.f, 0.f, 0.f);
    };
    auto doStore = [&](float4 A, float4 B0, float4 B1) {
        if (TM * 4 >= 256 || tid < TM * 4)
            *(float4*)&As[pA * 16 + e4] = A;
        float* d = &Bs[kk2B * 256 + c0B * 2];
        *(float4*)&d[0] = make_float4(B0.x, B1.x, B0.y, B1.y);
        *(float4*)&d[4] = make_float4(B0.z, B1.z, B0.w, B1.w);
    };

    float4 rA, rB0, rB1;
    doLoad(0, rA, rB0, rB1);
    doStore(rA, rB0, rB1);
    __syncthreads();

    for (int s = 0; s < S; s++) {
        float4 nA, nB0, nB1;
        if (s + 1 < S) doLoad(s + 1, nA, nB0, nB1);

#pragma unroll
        for (int kk2 = 0; kk2 < 8; kk2++) {
            u64 av[MR];
#pragma unroll
            for (int i = 0; i < MR; i++)
                av[i] = *(const u64*)&As[(m0 + i) * 16 + kk2 * 2];
            u64 bv[8];
#pragma unroll
            for (int mI = 0; mI < 4; mI++) {
                ulonglong2 t = *(const ulonglong2*)&Bs[kk2 * 256 + n0 * 2 + mI * 4];
                bv[2 * mI] = t.x; bv[2 * mI + 1] = t.y;
            }
#pragma unroll
            for (int i = 0; i < MR; i++)
#pragma unroll
                for (int j = 0; j < 8; j++) FMA2(acc[i][j], av[i], bv[j]);
        }
        __syncthreads();
        if (s + 1 < S) {
            doStore(nA, nB0, nB1);
            __syncthreads();
        }
    }

    // epilogue: bias + relu + per-position L2 norm over the 128 gram channels
    float bb[8];
    *(float4*)&bb[0] = *(const float4*)&bias[n0];
    *(float4*)&bb[4] = *(const float4*)&bias[n0 + 4];
#pragma unroll
    for (int i = 0; i < MR; i++) {
        float v[8];
        float ssq = 0.f;
#pragma unroll
        for (int j = 0; j < 8; j++) {
            float2 p2 = unpack2(acc[i][j]);
            float t = p2.x + p2.y + bb[j];
            t = fmaxf(t, 0.f);
            v[j] = t;
            ssq += t * t;
        }
        ssq += __shfl_xor_sync(0xffffffffu, ssq, 1);
        ssq += __shfl_xor_sync(0xffffffffu, ssq, 2);
        ssq += __shfl_xor_sync(0xffffffffu, ssq, 4);
        ssq += __shfl_xor_sync(0xffffffffu, ssq, 8);
        float inv = 1.f / (sqrtf(ssq) + 1e-13f);
        int p = p0 + m0 + i;
        if (p < L) {
            float* o = OUT + ((size_t)(b * L + p)) * 384 + g * 128 + n0;
            *(float4*)&o[0] = make_float4(v[0] * inv, v[1] * inv, v[2] * inv, v[3] * inv);
            *(float4*)&o[4] = make_float4(v[4] * inv, v[5] * inv, v[6] * inv, v[7] * inv);
        }
    }
}

// ---------------- kernel pooling (chunked doc tile, FFMA2 cos, 2-exp RBF) ----------------
__global__ __launch_bounds__(256) void pool2(const float* __restrict__ qmask,
                                             const float* __restrict__ dmask)
{
    extern __shared__ float sm[];
    float* ds   = sm;                  // 128*130
    float* qs   = sm + 128 * 130;      // 32*128
    float* qm   = qs + 32 * 128;       // 32
    float* dm   = qm + 32;             // 256
    float* wred = dm + 256;            // 88

    const int b    = blockIdx.x;
    const int pair = blockIdx.y;
    const int gi = pair / 3;
    const int gt = pair - gi * 3;
    const int tid = threadIdx.x;
    const int qq = tid >> 5;
    const int dd = tid & 31;

    const float* Db = g_D + ((size_t)b * ND) * 384 + gt * 128;
    const float* Qb = g_Q + ((size_t)b * NQ) * 384 + gi * 128;

#pragma unroll
    for (int it = 0; it < 16; it++) {
        int idx = tid + it * 256;
        int q = idx >> 7, c = idx & 127;
        qs[idx] = (q < NQ) ? Qb[q * 384 + c] : 0.f;
    }
    if (tid < 32) qm[tid] = (tid < NQ) ? qmask[b * NQ + tid] : 0.f;
    dm[tid] = dmask[b * ND + tid];

    float qacc[4][11];
#pragma unroll
    for (int i = 0; i < 4; i++)
#pragma unroll
        for (int kk = 0; kk < 11; kk++) qacc[i][kk] = 0.f;

    const float U1 = 0.13533528323661270f;   // e^-2
    const float U2 = 0.018315638888734179f;  // e^-4

    for (int chunk = 0; chunk < 2; chunk++) {
        // load 128-row doc chunk into ds[d][130] (k-contiguous, even stride for LDS.64)
#pragma unroll
        for (int it = 0; it < 16; it++) {
            int idx4 = tid + it * 256;
            int d  = idx4 >> 5;
            int c4 = (idx4 & 31) * 4;
            float4 v = *(const float4*)&Db[((size_t)(chunk * 128 + d)) * 384 + c4];
            float* dst = &ds[d * 130 + c4];
            *(float2*)&dst[0] = make_float2(v.x, v.y);
            *(float2*)&dst[2] = make_float2(v.z, v.w);
        }
        __syncthreads();

        u64 cos2[4][4];
#pragma unroll
        for (int i = 0; i < 4; i++)
#pragma unroll
            for (int ii = 0; ii < 4; ii++) cos2[i][ii] = 0ull;

#pragma unroll 4
        for (int k2 = 0; k2 < 64; k2++) {
            u64 a[4], dv[4];
#pragma unroll
            for (int i = 0; i < 4; i++)
                a[i] = *(const u64*)&qs[(qq * 4 + i) * 128 + 2 * k2];
#pragma unroll
            for (int ii = 0; ii < 4; ii++)
                dv[ii] = *(const u64*)&ds[(dd + 32 * ii) * 130 + 2 * k2];
#pragma unroll
            for (int i = 0; i < 4; i++)
#pragma unroll
                for (int ii = 0; ii < 4; ii++) FMA2(cos2[i][ii], a[i], dv[ii]);
        }

        // RBF accumulate. mu_j chain: v_j = e1 * t^(j-1) * u^((j-1)^2); valid since cos in [0,1].
#pragma unroll
        for (int i = 0; i < 4; i++) {
            float qmv = qm[qq * 4 + i];
#pragma unroll
            for (int ii = 0; ii < 4; ii++) {
                int d = chunk * 128 + dd + 32 * ii;
                float m = qmv * dm[d];
                float2 cc = unpack2(cos2[i][ii]);
                float c = (cc.x + cc.y) * m;
                float x = c - 0.9f;
                float e1 = __expf(-50.f * x * x) * m;
                float t  = __expf(-20.f * x);
                if (__any_sync(0xffffffffu, c > 0.98f)) {
                    float t0 = c - 1.0f;
                    qacc[i][0] += __expf(-500000.f * t0 * t0) * m;
                }
                float v = e1;
                qacc[i][1] += v;
                float r = t * U1;
#pragma unroll
                for (int j = 2; j < 11; j++) {
                    v *= r;
                    qacc[i][j] += v;
                    r *= U2;
                }
            }
        }
        __syncthreads();
    }

    // reduce per-(q,kernel) sums over the 32 dd lanes
#pragma unroll
    for (int i = 0; i < 4; i++)
#pragma unroll
        for (int kk = 0; kk < 11; kk++) {
            float v = qacc[i][kk];
            v += __shfl_xor_sync(0xffffffffu, v, 16);
            v += __shfl_xor_sync(0xffffffffu, v, 8);
            v += __shfl_xor_sync(0xffffffffu, v, 4);
            v += __shfl_xor_sync(0xffffffffu, v, 2);
            v += __shfl_xor_sync(0xffffffffu, v, 1);
            qacc[i][kk] = v;
        }

    if (dd == 0) {
        float part[11];
#pragma unroll
        for (int kk = 0; kk < 11; kk++) part[kk] = 0.f;
#pragma unroll
        for (int i = 0; i < 4; i++) {
            float qmv = qm[qq * 4 + i] * 0.01f;
#pragma unroll
            for (int kk = 0; kk < 11; kk++) {
                float pk = fmaxf(qacc[i][kk], 1e-10f);
                part[kk] += __logf(pk) * qmv;
            }
        }
#pragma unroll
        for (int kk = 0; kk < 11; kk++) wred[qq * 11 + kk] = part[kk];
    }
    __syncthreads();
    if (tid < 11) {
        float s = 0.f;
#pragma unroll
        for (int w = 0; w < 8; w++) s += wred[w * 11 + tid];
        g_feat[b * 99 + pair * 11 + tid] = s;
    }
}

// ---------------- final dense ----------------
__global__ void final_kernel(const float* __restrict__ dw, float* __restrict__ out)
{
    int b = threadIdx.x;
    if (b < NB) {
        float s = 0.f;
#pragma unroll
        for (int j = 0; j < 99; j++) s += g_feat[b * 99 + j] * dw[j];
        out[b] = s;
    }
}

// ---------------- launch ----------------
extern "C" void kernel_launch(void* const* d_in, const int* in_sizes, int n_in,
                              void* d_out, int out_size)
{
    const float* qe    = (const float*)d_in[0];
    const float* de    = (const float*)d_in[1];
    const float* qmask = (const float*)d_in[2];
    const float* dmask = (const float*)d_in[3];
    const float* w1    = (const float*)d_in[4];
    const float* b1    = (const float*)d_in[5];
    const float* w2    = (const float*)d_in[6];
    const float* b2    = (const float*)d_in[7];
    const float* w3    = (const float*)d_in[8];
    const float* b3    = (const float*)d_in[9];
    const float* dw    = (const float*)d_in[10];
    float* out = (float*)d_out;

    prep_wt<<<900, 256>>>(w1, w2, w3);
    prep_xq<<<(NB * 32 * 76 + 255) / 256, 256>>>(qe);
    prep_xd<<<(NB * ND * 76 + 255) / 256, 256>>>(de);

    conv2<32, 2, NQ, 32, true ><<<dim3(1, NB, 3), 256>>>(b1, b2, b3);
    conv2<64, 4, ND, ND, false><<<dim3(4, NB, 3), 256>>>(b1, b2, b3);

    int smem = (128 * 130 + 32 * 128 + 32 + 256 + 88) * (int)sizeof(float);
    cudaFuncSetAttribute(pool2, cudaFuncAttributeMaxDynamicSharedMemorySize, smem);
    pool2<<<dim3(NB, 9), 256, smem>>>(qmask, dmask);

    final_kernel<<<1, 128>>>(dw, out);
}

// round 4
// speedup vs baseline: 3.7517x; 3.7517x over previous
#include <cuda_runtime.h>
#include <cuda_bf16.h>
#include <math.h>
#include <cstdint>

#define NB 128
#define NQ 30
#define ND 256
#define NE 300
#define KP 320                 // padded K per tap (5 chunks of 64)
#define XQROWS 34              // 32 M rows + 2 tap guard
#define XDROWS 258             // 256 + 2 tap guard

// ---------------- scratch (16B aligned for uint4 access) ----------------
__device__ __align__(16) __nv_bfloat16 g_Xqh[NB * XQROWS * KP];
__device__ __align__(16) __nv_bfloat16 g_Xql[NB * XQROWS * KP];
__device__ __align__(16) __nv_bfloat16 g_Xdh[NB * XDROWS * KP];
__device__ __align__(16) __nv_bfloat16 g_Xdl[NB * XDROWS * KP];
__device__ __align__(16) __nv_bfloat16 g_Wh[245760];   // [g][n][tap][320]
__device__ __align__(16) __nv_bfloat16 g_Wl[245760];
__device__ float g_Q[NB * NQ * 384];
__device__ float g_D[NB * ND * 384];
__device__ float g_feat[NB * 99];

__device__ __forceinline__ uint32_t smem_u32(const void* p) {
    uint32_t a;
    asm("{ .reg .u64 t; cvta.to.shared.u64 t, %1; cvt.u32.u64 %0, t; }" : "=r"(a) : "l"(p));
    return a;
}
__device__ __forceinline__ void ldsm4(uint32_t* r, uint32_t addr) {
    asm volatile("ldmatrix.sync.aligned.m8n8.x4.shared.b16 {%0,%1,%2,%3}, [%4];"
                 : "=r"(r[0]), "=r"(r[1]), "=r"(r[2]), "=r"(r[3]) : "r"(addr));
}
__device__ __forceinline__ void mma16816(float* c, const uint32_t* a, const uint32_t* b) {
    asm volatile("mma.sync.aligned.m16n8k16.row.col.f32.bf16.bf16.f32 "
                 "{%0,%1,%2,%3}, {%4,%5,%6,%7}, {%8,%9}, {%0,%1,%2,%3};"
                 : "+f"(c[0]), "+f"(c[1]), "+f"(c[2]), "+f"(c[3])
                 : "r"(a[0]), "r"(a[1]), "r"(a[2]), "r"(a[3]), "r"(b[0]), "r"(b[1]));
}

// ---------------- prep: weights -> bf16 hi/lo, [n][tap][320] per gram ----------------
__global__ __launch_bounds__(256) void prep_w(const float* __restrict__ w1,
                                              const float* __restrict__ w2,
                                              const float* __restrict__ w3)
{
    int idx = blockIdx.x * 256 + threadIdx.x;
    if (idx >= 245760) return;
    int g, base, rs;
    if (idx < 40960)       { g = 0; base = 0;      rs = 320; }
    else if (idx < 122880) { g = 1; base = 40960;  rs = 640; }
    else                   { g = 2; base = 122880; rs = 960; }
    int off = idx - base;
    int n = off / rs;
    int r = off - n * rs;
    int tap = r / KP;
    int e = r - tap * KP;
    float v = 0.f;
    if (e < NE) {
        const float* w = (g == 0) ? w1 : ((g == 1) ? w2 : w3);
        v = w[(n * NE + e) * (g + 1) + tap];
    }
    __nv_bfloat16 h = __float2bfloat16(v);
    g_Wh[idx] = h;
    g_Wl[idx] = __float2bfloat16(v - __bfloat162float(h));
}

// ---------------- prep: embeddings -> padded bf16 hi/lo ----------------
template<int ROWS, int LVALID>
__global__ __launch_bounds__(256) void prep_x(const float* __restrict__ X,
                                              __nv_bfloat16* __restrict__ Xh,
                                              __nv_bfloat16* __restrict__ Xl)
{
    int idx = blockIdx.x * 256 + threadIdx.x;
    const int T = NB * ROWS * (KP / 4);
    if (idx >= T) return;
    int e4  = idx % (KP / 4);
    int row = idx / (KP / 4);
    int b = row / ROWS;
    int p = row - b * ROWS;
    int e0 = e4 * 4;
    float4 v = make_float4(0.f, 0.f, 0.f, 0.f);
    if (p < LVALID && e0 < NE)
        v = *(const float4*)&X[((size_t)(b * LVALID + p)) * NE + e0];
    __nv_bfloat16 h[4], l[4];
    float vv[4] = {v.x, v.y, v.z, v.w};
#pragma unroll
    for (int j = 0; j < 4; j++) {
        h[j] = __float2bfloat16(vv[j]);
        l[j] = __float2bfloat16(vv[j] - __bfloat162float(h[j]));
    }
    size_t o = (size_t)row * KP + e0;
    *(__nv_bfloat162*)&Xh[o]     = *(__nv_bfloat162*)&h[0];
    *(__nv_bfloat162*)&Xh[o + 2] = *(__nv_bfloat162*)&h[2];
    *(__nv_bfloat162*)&Xl[o]     = *(__nv_bfloat162*)&l[0];
    *(__nv_bfloat162*)&Xl[o + 2] = *(__nv_bfloat162*)&l[2];
}

// ---------------- conv GEMM via mma.sync (bf16 split, fp32 accum) ----------------
// C[TM,128] = sum_K A[TM,K] * W[128,K]^T per (mtile, b, g). K chunk = 64.
// smem rows padded to stride 72 bf16 (144B) -> ldmatrix conflict-free.
template<int TM, int WC, int XR, int LVALID, bool IS_Q>
__global__ __launch_bounds__(256) void convmma(const float* __restrict__ bs0,
                                               const float* __restrict__ bs1,
                                               const float* __restrict__ bs2)
{
    constexpr int NWN   = 128 / WC;      // warp n-extent
    constexpr int NFRAG = NWN / 8;       // n8 frags per warp
    constexpr int NJ2   = NFRAG / 2;     // ldmatrix.x4 B loads per k-step
    constexpr int SA    = 72;            // smem row stride (bf16)
    constexpr int AH = 0;
    constexpr int AL = TM * 144;
    constexpr int BH = 2 * TM * 144;
    constexpr int BL = BH + 18432;       // 128*144
    constexpr int SQ = BL + 18432;

    extern __shared__ char sm[];
    const uint32_t sbase = smem_u32(sm);

    const int tid  = threadIdx.x;
    const int wid  = tid >> 5;
    const int lane = tid & 31;
    const int wr = wid / WC;
    const int wcn = wid % WC;
    const int mr = wr * 32;
    const int nc = wcn * NWN;

    const int g  = blockIdx.z;
    const int b  = blockIdx.y;
    const int m0 = blockIdx.x * TM;
    const int wbase = (g == 0) ? 0 : ((g == 1) ? 40960 : 122880);
    const int wrs = (g + 1) * KP;
    const float* bias = (g == 0) ? bs0 : ((g == 1) ? bs1 : bs2);
    const __nv_bfloat16* Xh = (IS_Q ? g_Xqh : g_Xdh) + (size_t)b * XR * KP;
    const __nv_bfloat16* Xl = (IS_Q ? g_Xql : g_Xdl) + (size_t)b * XR * KP;
    float* OUT = IS_Q ? g_Q : g_D;

    if (tid < TM) *(float*)(sm + SQ + tid * 4) = 0.f;

    // ldmatrix lane offsets (bytes)
    const int lg = lane >> 3, l7 = lane & 7;
    const uint32_t a_off = ((mr + (lg & 1) * 8 + l7) * SA + ((lg >> 1) * 8)) * 2;
    const uint32_t b_off = ((nc + (lg >> 1) * 8 + l7) * SA + ((lg & 1) * 8)) * 2;

    float acc[2][NFRAG][4];
#pragma unroll
    for (int f = 0; f < 2; f++)
#pragma unroll
        for (int j = 0; j < NFRAG; j++)
#pragma unroll
            for (int t = 0; t < 4; t++) acc[f][j][t] = 0.f;

    const int NCC = 5 * (g + 1);
    for (int cc = 0; cc < NCC; cc++) {
        int tap = cc / 5;
        int e0 = (cc - tap * 5) * 64;
        const __nv_bfloat16* ah = Xh + (size_t)(m0 + tap) * KP + e0;
        const __nv_bfloat16* al = Xl + (size_t)(m0 + tap) * KP + e0;
        const __nv_bfloat16* bh = g_Wh + wbase + tap * KP + e0;
        const __nv_bfloat16* bl = g_Wl + wbase + tap * KP + e0;

        __syncthreads();
#pragma unroll
        for (int u = tid; u < TM * 8; u += 256) {
            int r = u >> 3, c = u & 7;
            *(uint4*)(sm + AH + r * 144 + c * 16) = *(const uint4*)(ah + (size_t)r * KP + c * 8);
            *(uint4*)(sm + AL + r * 144 + c * 16) = *(const uint4*)(al + (size_t)r * KP + c * 8);
        }
#pragma unroll
        for (int u = tid; u < 1024; u += 256) {
            int r = u >> 3, c = u & 7;
            *(uint4*)(sm + BH + r * 144 + c * 16) = *(const uint4*)(bh + (size_t)r * wrs + c * 8);
            *(uint4*)(sm + BL + r * 144 + c * 16) = *(const uint4*)(bl + (size_t)r * wrs + c * 8);
        }
        __syncthreads();

#pragma unroll
        for (int ks = 0; ks < 4; ks++) {
            uint32_t ahf[2][4], alf[2][4];
            ldsm4(ahf[0], sbase + AH + a_off + ks * 32);
            ldsm4(ahf[1], sbase + AH + a_off + 16 * SA * 2 + ks * 32);
            ldsm4(alf[0], sbase + AL + a_off + ks * 32);
            ldsm4(alf[1], sbase + AL + a_off + 16 * SA * 2 + ks * 32);
            uint32_t bhf[NJ2][4], blf[NJ2][4];
#pragma unroll
            for (int j2 = 0; j2 < NJ2; j2++) {
                ldsm4(bhf[j2], sbase + BH + b_off + j2 * 16 * SA * 2 + ks * 32);
                ldsm4(blf[j2], sbase + BL + b_off + j2 * 16 * SA * 2 + ks * 32);
            }
#pragma unroll
            for (int f = 0; f < 2; f++)
#pragma unroll
                for (int j = 0; j < NFRAG; j++) {
                    const uint32_t* bhp = &bhf[j >> 1][(j & 1) * 2];
                    const uint32_t* blp = &blf[j >> 1][(j & 1) * 2];
                    mma16816(acc[f][j], ahf[f], bhp);
                    mma16816(acc[f][j], ahf[f], blp);
                    mma16816(acc[f][j], alf[f], bhp);
                }
        }
    }

    // ---------------- epilogue: bias + relu + rowwise L2 norm ----------------
    const int lq = lane >> 2, lr = lane & 3;
    float ssq_p[2][2] = {{0.f, 0.f}, {0.f, 0.f}};
#pragma unroll
    for (int f = 0; f < 2; f++)
#pragma unroll
        for (int j = 0; j < NFRAG; j++) {
            float bv0 = __ldg(&bias[nc + j * 8 + 2 * lr]);
            float bv1 = __ldg(&bias[nc + j * 8 + 2 * lr + 1]);
            float v0 = fmaxf(acc[f][j][0] + bv0, 0.f);
            float v1 = fmaxf(acc[f][j][1] + bv1, 0.f);
            float v2 = fmaxf(acc[f][j][2] + bv0, 0.f);
            float v3 = fmaxf(acc[f][j][3] + bv1, 0.f);
            acc[f][j][0] = v0; acc[f][j][1] = v1; acc[f][j][2] = v2; acc[f][j][3] = v3;
            ssq_p[f][0] += v0 * v0 + v1 * v1;
            ssq_p[f][1] += v2 * v2 + v3 * v3;
        }
#pragma unroll
    for (int f = 0; f < 2; f++)
#pragma unroll
        for (int h = 0; h < 2; h++) {
            float v = ssq_p[f][h];
            v += __shfl_xor_sync(0xffffffffu, v, 1);
            v += __shfl_xor_sync(0xffffffffu, v, 2);
            if (lr == 0)
                atomicAdd((float*)(sm + SQ + (mr + f * 16 + h * 8 + lq) * 4), v);
        }
    __syncthreads();

#pragma unroll
    for (int f = 0; f < 2; f++) {
        int row0 = mr + f * 16 + lq;
        float s0 = *(float*)(sm + SQ + row0 * 4);
        float s1 = *(float*)(sm + SQ + (row0 + 8) * 4);
        float inv0 = 1.f / (sqrtf(s0) + 1e-13f);
        float inv1 = 1.f / (sqrtf(s1) + 1e-13f);
        int p0 = m0 + row0, p1 = m0 + row0 + 8;
#pragma unroll
        for (int j = 0; j < NFRAG; j++) {
            int ch = nc + j * 8 + 2 * lr;
            if (p0 < LVALID)
                *(float2*)&OUT[((size_t)(b * LVALID + p0)) * 384 + g * 128 + ch] =
                    make_float2(acc[f][j][0] * inv0, acc[f][j][1] * inv0);
            if (p1 < LVALID)
                *(float2*)&OUT[((size_t)(b * LVALID + p1)) * 384 + g * 128 + ch] =
                    make_float2(acc[f][j][2] * inv1, acc[f][j][3] * inv1);
        }
    }
}

// ---------------- kernel pooling (round-1 proven version) ----------------
__global__ __launch_bounds__(256) void pool_kernel(const float* __restrict__ qmask,
                                                   const float* __restrict__ dmask)
{
    extern __shared__ float smf[];
    float* ds   = smf;
    float* qs   = smf + 256 * 129;
    float* qm   = qs + 32 * 128;
    float* dm   = qm + 32;
    float* wred = dm + 256;

    const int b    = blockIdx.x;
    const int pair = blockIdx.y;
    const int gi = pair / 3;
    const int gt = pair - gi * 3;
    const int tid = threadIdx.x;

    const float* Db = g_D + ((size_t)b * ND) * 384 + gt * 128;
    const float* Qb = g_Q + ((size_t)b * NQ) * 384 + gi * 128;

#pragma unroll 4
    for (int it = 0; it < 32; it++) {
        int idx4 = tid + it * 256;
        int d  = idx4 >> 5;
        int c4 = (idx4 & 31) * 4;
        float4 v = *(const float4*)&Db[(size_t)d * 384 + c4];
        float* dst = &ds[d * 129 + c4];
        dst[0] = v.x; dst[1] = v.y; dst[2] = v.z; dst[3] = v.w;
    }
#pragma unroll
    for (int it = 0; it < 16; it++) {
        int idx = tid + it * 256;
        int q = idx >> 7;
        int c = idx & 127;
        qs[idx] = (q < NQ) ? Qb[q * 384 + c] : 0.f;
    }
    if (tid < 32)  qm[tid] = (tid < NQ) ? qmask[b * NQ + tid] : 0.f;
    dm[tid] = dmask[b * ND + tid];
    __syncthreads();

    const int qq = tid >> 5;
    const int dd = tid & 31;

    float cosv[4][8];
#pragma unroll
    for (int i = 0; i < 4; i++)
#pragma unroll
        for (int ii = 0; ii < 8; ii++) cosv[i][ii] = 0.f;

#pragma unroll 2
    for (int k = 0; k < 128; k++) {
        float qv0 = qs[(qq * 4 + 0) * 128 + k];
        float qv1 = qs[(qq * 4 + 1) * 128 + k];
        float qv2 = qs[(qq * 4 + 2) * 128 + k];
        float qv3 = qs[(qq * 4 + 3) * 128 + k];
#pragma unroll
        for (int ii = 0; ii < 8; ii++) {
            float dv = ds[(dd + 32 * ii) * 129 + k];
            cosv[0][ii] += qv0 * dv;
            cosv[1][ii] += qv1 * dv;
            cosv[2][ii] += qv2 * dv;
            cosv[3][ii] += qv3 * dv;
        }
    }

    float qacc[4][11];
#pragma unroll
    for (int i = 0; i < 4; i++)
#pragma unroll
        for (int kk2 = 0; kk2 < 11; kk2++) qacc[i][kk2] = 0.f;

    const float U1 = 0.13533528323661270f;   // e^-2
    const float U2 = 0.018315638888734179f;  // e^-4
#pragma unroll
    for (int i = 0; i < 4; i++) {
        float qmv = qm[qq * 4 + i];
#pragma unroll
        for (int ii = 0; ii < 8; ii++) {
            int d = dd + 32 * ii;
            float m = qmv * dm[d];
            float c = cosv[i][ii] * m;
            float x = c - 0.9f;
            float e1 = __expf(-50.f * x * x) * m;
            float t  = __expf(-20.f * x);
            float t0 = c - 1.0f;
            qacc[i][0] += __expf(-500000.f * t0 * t0) * m;
            float v = e1;
            qacc[i][1] += v;
            float r = t * U1;
#pragma unroll
            for (int j = 2; j < 11; j++) {
                v *= r;
                qacc[i][j] += v;
                r *= U2;
            }
        }
    }

#pragma unroll
    for (int i = 0; i < 4; i++)
#pragma unroll
        for (int kk2 = 0; kk2 < 11; kk2++) {
            float v = qacc[i][kk2];
            v += __shfl_xor_sync(0xffffffffu, v, 16);
            v += __shfl_xor_sync(0xffffffffu, v, 8);
            v += __shfl_xor_sync(0xffffffffu, v, 4);
            v += __shfl_xor_sync(0xffffffffu, v, 2);
            v += __shfl_xor_sync(0xffffffffu, v, 1);
            qacc[i][kk2] = v;
        }

    if (dd == 0) {
        float part[11];
#pragma unroll
        for (int kk2 = 0; kk2 < 11; kk2++) part[kk2] = 0.f;
#pragma unroll
        for (int i = 0; i < 4; i++) {
            float qmv = qm[qq * 4 + i] * 0.01f;
#pragma unroll
            for (int kk2 = 0; kk2 < 11; kk2++) {
                float pk = fmaxf(qacc[i][kk2], 1e-10f);
                part[kk2] += __logf(pk) * qmv;
            }
        }
#pragma unroll
        for (int kk2 = 0; kk2 < 11; kk2++) wred[qq * 11 + kk2] = part[kk2];
    }
    __syncthreads();
    if (tid < 11) {
        float s = 0.f;
#pragma unroll
        for (int w = 0; w < 8; w++) s += wred[w * 11 + tid];
        g_feat[b * 99 + pair * 11 + tid] = s;
    }
}

// ---------------- final dense ----------------
__global__ void final_kernel(const float* __restrict__ dw, float* __restrict__ out)
{
    int b = threadIdx.x;
    if (b < NB) {
        float s = 0.f;
#pragma unroll
        for (int j = 0; j < 99; j++) s += g_feat[b * 99 + j] * dw[j];
        out[b] = s;
    }
}

// ---------------- launch ----------------
extern "C" void kernel_launch(void* const* d_in, const int* in_sizes, int n_in,
                              void* d_out, int out_size)
{
    const float* qe    = (const float*)d_in[0];
    const float* de    = (const float*)d_in[1];
    const float* qmask = (const float*)d_in[2];
    const float* dmask = (const float*)d_in[3];
    const float* w1    = (const float*)d_in[4];
    const float* b1    = (const float*)d_in[5];
    const float* w2    = (const float*)d_in[6];
    const float* b2    = (const float*)d_in[7];
    const float* w3    = (const float*)d_in[8];
    const float* b3    = (const float*)d_in[9];
    const float* dw    = (const float*)d_in[10];
    float* out = (float*)d_out;

    __nv_bfloat16 *xqh, *xql, *xdh, *xdl;
    cudaGetSymbolAddress((void**)&xqh, g_Xqh);
    cudaGetSymbolAddress((void**)&xql, g_Xql);
    cudaGetSymbolAddress((void**)&xdh, g_Xdh);
    cudaGetSymbolAddress((void**)&xdl, g_Xdl);

    prep_w<<<(245760 + 255) / 256, 256>>>(w1, w2, w3);
    prep_x<XQROWS, NQ><<<(NB * XQROWS * (KP / 4) + 255) / 256, 256>>>(qe, xqh, xql);
    prep_x<XDROWS, ND><<<(NB * XDROWS * (KP / 4) + 255) / 256, 256>>>(de, xdh, xdl);

    const int SMEMD = 2 * 128 * 144 + 2 * 18432 + 128 * 4;  // 74240
    const int SMEMQ = 2 * 32 * 144 + 2 * 18432 + 128 * 4;   // 46592
    cudaFuncSetAttribute(convmma<32, 8, XQROWS, NQ, true >, cudaFuncAttributeMaxDynamicSharedMemorySize, SMEMQ);
    cudaFuncSetAttribute(convmma<128, 2, XDROWS, ND, false>, cudaFuncAttributeMaxDynamicSharedMemorySize, SMEMD);
    convmma<32, 8, XQROWS, NQ, true ><<<dim3(1, NB, 3), 256, SMEMQ>>>(b1, b2, b3);
    convmma<128, 2, XDROWS, ND, false><<<dim3(2, NB, 3), 256, SMEMD>>>(b1, b2, b3);

    int smem = (256 * 129 + 32 * 128 + 32 + 256 + 88) * (int)sizeof(float);
    cudaFuncSetAttribute(pool_kernel, cudaFuncAttributeMaxDynamicSharedMemorySize, smem);
    pool_kernel<<<dim3(NB, 9), 256, smem>>>(qmask, dmask);

    final_kernel<<<1, 128>>>(dw, out);
}

// round 7
// speedup vs baseline: 4.2228x; 1.1256x over previous
#include <cuda_runtime.h>
#include <cuda_bf16.h>
#include <math.h>
#include <cstdint>

#define NB 128
#define NQ 30
#define ND 256
#define NE 300
#define KP 320
#define XQROWS 34
#define XDROWS 258

// ---------------- scratch ----------------
__device__ __align__(16) __nv_bfloat16 g_Xqh[NB * XQROWS * KP];
__device__ __align__(16) __nv_bfloat16 g_Xql[NB * XQROWS * KP];
__device__ __align__(16) __nv_bfloat16 g_Xdh[NB * XDROWS * KP];
__device__ __align__(16) __nv_bfloat16 g_Xdl[NB * XDROWS * KP];
__device__ __align__(16) __nv_bfloat16 g_Wh[245760];
__device__ __align__(16) __nv_bfloat16 g_Wl[245760];
__device__ __align__(16) float g_Q[NB * NQ * 384];
__device__ __align__(16) float g_D[NB * ND * 384];
__device__ __align__(16) __nv_bfloat16 g_Qh2[NB * 32 * 384];   // 32 rows/b, rows>=30 zero
__device__ __align__(16) __nv_bfloat16 g_Ql2[NB * 32 * 384];
__device__ __align__(16) __nv_bfloat16 g_Dh2[NB * ND * 384];
__device__ __align__(16) __nv_bfloat16 g_Dl2[NB * ND * 384];
__device__ float g_pk[NB * 9 * 30 * 11];
__device__ float g_feat[NB * 99];

__device__ __forceinline__ uint32_t smem_u32(const void* p) {
    uint32_t a;
    asm("{ .reg .u64 t; cvta.to.shared.u64 t, %1; cvt.u32.u64 %0, t; }" : "=r"(a) : "l"(p));
    return a;
}
__device__ __forceinline__ void ldsm4(uint32_t* r, uint32_t addr) {
    asm volatile("ldmatrix.sync.aligned.m8n8.x4.shared.b16 {%0,%1,%2,%3}, [%4];"
                 : "=r"(r[0]), "=r"(r[1]), "=r"(r[2]), "=r"(r[3]) : "r"(addr));
}
__device__ __forceinline__ void mma16816(float* c, const uint32_t* a, const uint32_t* b) {
    asm volatile("mma.sync.aligned.m16n8k16.row.col.f32.bf16.bf16.f32 "
                 "{%0,%1,%2,%3}, {%4,%5,%6,%7}, {%8,%9}, {%0,%1,%2,%3};"
                 : "+f"(c[0]), "+f"(c[1]), "+f"(c[2]), "+f"(c[3])
                 : "r"(a[0]), "r"(a[1]), "r"(a[2]), "r"(a[3]), "r"(b[0]), "r"(b[1]));
}

// ---------------- prep kernels (proven) ----------------
__global__ __launch_bounds__(256) void prep_w(const float* __restrict__ w1,
                                              const float* __restrict__ w2,
                                              const float* __restrict__ w3)
{
    int idx = blockIdx.x * 256 + threadIdx.x;
    if (idx >= 245760) return;
    int g, base, rs;
    if (idx < 40960)       { g = 0; base = 0;      rs = 320; }
    else if (idx < 122880) { g = 1; base = 40960;  rs = 640; }
    else                   { g = 2; base = 122880; rs = 960; }
    int off = idx - base;
    int n = off / rs;
    int r = off - n * rs;
    int tap = r / KP;
    int e = r - tap * KP;
    float v = 0.f;
    if (e < NE) {
        const float* w = (g == 0) ? w1 : ((g == 1) ? w2 : w3);
        v = w[(n * NE + e) * (g + 1) + tap];
    }
    __nv_bfloat16 h = __float2bfloat16(v);
    g_Wh[idx] = h;
    g_Wl[idx] = __float2bfloat16(v - __bfloat162float(h));
}

template<int ROWS, int LVALID>
__global__ __launch_bounds__(256) void prep_x(const float* __restrict__ X,
                                              __nv_bfloat16* __restrict__ Xh,
                                              __nv_bfloat16* __restrict__ Xl)
{
    int idx = blockIdx.x * 256 + threadIdx.x;
    const int T = NB * ROWS * (KP / 4);
    if (idx >= T) return;
    int e4  = idx % (KP / 4);
    int row = idx / (KP / 4);
    int b = row / ROWS;
    int p = row - b * ROWS;
    int e0 = e4 * 4;
    float4 v = make_float4(0.f, 0.f, 0.f, 0.f);
    if (p < LVALID && e0 < NE)
        v = *(const float4*)&X[((size_t)(b * LVALID + p)) * NE + e0];
    __nv_bfloat16 h[4], l[4];
    float vv[4] = {v.x, v.y, v.z, v.w};
#pragma unroll
    for (int j = 0; j < 4; j++) {
        h[j] = __float2bfloat16(vv[j]);
        l[j] = __float2bfloat16(vv[j] - __bfloat162float(h[j]));
    }
    size_t o = (size_t)row * KP + e0;
    *(__nv_bfloat162*)&Xh[o]     = *(__nv_bfloat162*)&h[0];
    *(__nv_bfloat162*)&Xh[o + 2] = *(__nv_bfloat162*)&h[2];
    *(__nv_bfloat162*)&Xl[o]     = *(__nv_bfloat162*)&l[0];
    *(__nv_bfloat162*)&Xl[o + 2] = *(__nv_bfloat162*)&l[2];
}

// ---------------- conv GEMM via mma.sync (round-4 proven, verbatim) ----------------
template<int TM, int WC, int XR, int LVALID, bool IS_Q>
__global__ __launch_bounds__(256) void convmma(const float* __restrict__ bs0,
                                               const float* __restrict__ bs1,
                                               const float* __restrict__ bs2)
{
    constexpr int NWN   = 128 / WC;
    constexpr int NFRAG = NWN / 8;
    constexpr int NJ2   = NFRAG / 2;
    constexpr int SA    = 72;
    constexpr int AH = 0;
    constexpr int AL = TM * 144;
    constexpr int BH = 2 * TM * 144;
    constexpr int BL = BH + 18432;
    constexpr int SQ = BL + 18432;

    extern __shared__ char sm[];
    const uint32_t sbase = smem_u32(sm);

    const int tid  = threadIdx.x;
    const int wid  = tid >> 5;
    const int lane = tid & 31;
    const int wr = wid / WC;
    const int wcn = wid % WC;
    const int mr = wr * 32;
    const int nc = wcn * NWN;

    const int g  = blockIdx.z;
    const int b  = blockIdx.y;
    const int m0 = blockIdx.x * TM;
    const int wbase = (g == 0) ? 0 : ((g == 1) ? 40960 : 122880);
    const int wrs = (g + 1) * KP;
    const float* bias = (g == 0) ? bs0 : ((g == 1) ? bs1 : bs2);
    const __nv_bfloat16* Xh = (IS_Q ? g_Xqh : g_Xdh) + (size_t)b * XR * KP;
    const __nv_bfloat16* Xl = (IS_Q ? g_Xql : g_Xdl) + (size_t)b * XR * KP;
    float* OUT = IS_Q ? g_Q : g_D;

    if (tid < TM) *(float*)(sm + SQ + tid * 4) = 0.f;

    const int lg = lane >> 3, l7 = lane & 7;
    const uint32_t a_off = ((mr + (lg & 1) * 8 + l7) * SA + ((lg >> 1) * 8)) * 2;
    const uint32_t b_off = ((nc + (lg >> 1) * 8 + l7) * SA + ((lg & 1) * 8)) * 2;

    float acc[2][NFRAG][4];
#pragma unroll
    for (int f = 0; f < 2; f++)
#pragma unroll
        for (int j = 0; j < NFRAG; j++)
#pragma unroll
            for (int t = 0; t < 4; t++) acc[f][j][t] = 0.f;

    const int NCC = 5 * (g + 1);
    for (int cc = 0; cc < NCC; cc++) {
        int tap = cc / 5;
        int e0 = (cc - tap * 5) * 64;
        const __nv_bfloat16* ah = Xh + (size_t)(m0 + tap) * KP + e0;
        const __nv_bfloat16* al = Xl + (size_t)(m0 + tap) * KP + e0;
        const __nv_bfloat16* bh = g_Wh + wbase + tap * KP + e0;
        const __nv_bfloat16* bl = g_Wl + wbase + tap * KP + e0;

        __syncthreads();
#pragma unroll
        for (int u = tid; u < TM * 8; u += 256) {
            int r = u >> 3, c = u & 7;
            *(uint4*)(sm + AH + r * 144 + c * 16) = *(const uint4*)(ah + (size_t)r * KP + c * 8);
            *(uint4*)(sm + AL + r * 144 + c * 16) = *(const uint4*)(al + (size_t)r * KP + c * 8);
        }
#pragma unroll
        for (int u = tid; u < 1024; u += 256) {
            int r = u >> 3, c = u & 7;
            *(uint4*)(sm + BH + r * 144 + c * 16) = *(const uint4*)(bh + (size_t)r * wrs + c * 8);
            *(uint4*)(sm + BL + r * 144 + c * 16) = *(const uint4*)(bl + (size_t)r * wrs + c * 8);
        }
        __syncthreads();

#pragma unroll
        for (int ks = 0; ks < 4; ks++) {
            uint32_t ahf[2][4], alf[2][4];
            ldsm4(ahf[0], sbase + AH + a_off + ks * 32);
            ldsm4(ahf[1], sbase + AH + a_off + 16 * SA * 2 + ks * 32);
            ldsm4(alf[0], sbase + AL + a_off + ks * 32);
            ldsm4(alf[1], sbase + AL + a_off + 16 * SA * 2 + ks * 32);
            uint32_t bhf[NJ2][4], blf[NJ2][4];
#pragma unroll
            for (int j2 = 0; j2 < NJ2; j2++) {
                ldsm4(bhf[j2], sbase + BH + b_off + j2 * 16 * SA * 2 + ks * 32);
                ldsm4(blf[j2], sbase + BL + b_off + j2 * 16 * SA * 2 + ks * 32);
            }
#pragma unroll
            for (int f = 0; f < 2; f++)
#pragma unroll
                for (int j = 0; j < NFRAG; j++) {
                    const uint32_t* bhp = &bhf[j >> 1][(j & 1) * 2];
                    const uint32_t* blp = &blf[j >> 1][(j & 1) * 2];
                    mma16816(acc[f][j], ahf[f], bhp);
                    mma16816(acc[f][j], ahf[f], blp);
                    mma16816(acc[f][j], alf[f], bhp);
                }
        }
    }

    const int lq = lane >> 2, lr = lane & 3;
    float ssq_p[2][2] = {{0.f, 0.f}, {0.f, 0.f}};
#pragma unroll
    for (int f = 0; f < 2; f++)
#pragma unroll
        for (int j = 0; j < NFRAG; j++) {
            float bv0 = __ldg(&bias[nc + j * 8 + 2 * lr]);
            float bv1 = __ldg(&bias[nc + j * 8 + 2 * lr + 1]);
            float v0 = fmaxf(acc[f][j][0] + bv0, 0.f);
            float v1 = fmaxf(acc[f][j][1] + bv1, 0.f);
            float v2 = fmaxf(acc[f][j][2] + bv0, 0.f);
            float v3 = fmaxf(acc[f][j][3] + bv1, 0.f);
            acc[f][j][0] = v0; acc[f][j][1] = v1; acc[f][j][2] = v2; acc[f][j][3] = v3;
            ssq_p[f][0] += v0 * v0 + v1 * v1;
            ssq_p[f][1] += v2 * v2 + v3 * v3;
        }
#pragma unroll
    for (int f = 0; f < 2; f++)
#pragma unroll
        for (int h = 0; h < 2; h++) {
            float v = ssq_p[f][h];
            v += __shfl_xor_sync(0xffffffffu, v, 1);
            v += __shfl_xor_sync(0xffffffffu, v, 2);
            if (lr == 0)
                atomicAdd((float*)(sm + SQ + (mr + f * 16 + h * 8 + lq) * 4), v);
        }
    __syncthreads();

#pragma unroll
    for (int f = 0; f < 2; f++) {
        int row0 = mr + f * 16 + lq;
        float s0 = *(float*)(sm + SQ + row0 * 4);
        float s1 = *(float*)(sm + SQ + (row0 + 8) * 4);
        float inv0 = 1.f / (sqrtf(s0) + 1e-13f);
        float inv1 = 1.f / (sqrtf(s1) + 1e-13f);
        int p0 = m0 + row0, p1 = m0 + row0 + 8;
#pragma unroll
        for (int j = 0; j < NFRAG; j++) {
            int ch = nc + j * 8 + 2 * lr;
            if (p0 < LVALID)
                *(float2*)&OUT[((size_t)(b * LVALID + p0)) * 384 + g * 128 + ch] =
                    make_float2(acc[f][j][0] * inv0, acc[f][j][1] * inv0);
            if (p1 < LVALID)
                *(float2*)&OUT[((size_t)(b * LVALID + p1)) * 384 + g * 128 + ch] =
                    make_float2(acc[f][j][2] * inv1, acc[f][j][3] * inv1);
        }
    }
}

// ---------------- splitters ----------------
__global__ __launch_bounds__(256) void split_q(const float* __restrict__ S,
                                               __nv_bfloat16* __restrict__ H,
                                               __nv_bfloat16* __restrict__ L)
{
    int i = blockIdx.x * 256 + threadIdx.x;           // float4 index
    const int T = NB * 32 * 96;
    if (i >= T) return;
    int c4 = i % 96;
    int rb = i / 96;
    int r = rb & 31, b = rb >> 5;
    float4 v = make_float4(0.f, 0.f, 0.f, 0.f);
    if (r < NQ) v = *(const float4*)&S[((size_t)(b * NQ + r)) * 384 + c4 * 4];
    float vv[4] = {v.x, v.y, v.z, v.w};
    __nv_bfloat16 h[4], l[4];
#pragma unroll
    for (int j = 0; j < 4; j++) {
        h[j] = __float2bfloat16(vv[j]);
        l[j] = __float2bfloat16(vv[j] - __bfloat162float(h[j]));
    }
    size_t o = (size_t)i * 4;
    *(__nv_bfloat162*)&H[o]     = *(__nv_bfloat162*)&h[0];
    *(__nv_bfloat162*)&H[o + 2] = *(__nv_bfloat162*)&h[2];
    *(__nv_bfloat162*)&L[o]     = *(__nv_bfloat162*)&l[0];
    *(__nv_bfloat162*)&L[o + 2] = *(__nv_bfloat162*)&l[2];
}

__global__ __launch_bounds__(256) void split_hl(const float* __restrict__ S,
                                                __nv_bfloat16* __restrict__ H,
                                                __nv_bfloat16* __restrict__ L, int n4)
{
    int i = blockIdx.x * 256 + threadIdx.x;
    if (i >= n4) return;
    float4 v = ((const float4*)S)[i];
    float vv[4] = {v.x, v.y, v.z, v.w};
    __nv_bfloat16 h[4], l[4];
#pragma unroll
    for (int j = 0; j < 4; j++) {
        h[j] = __float2bfloat16(vv[j]);
        l[j] = __float2bfloat16(vv[j] - __bfloat162float(h[j]));
    }
    size_t o = (size_t)i * 4;
    *(__nv_bfloat162*)&H[o]     = *(__nv_bfloat162*)&h[0];
    *(__nv_bfloat162*)&H[o + 2] = *(__nv_bfloat162*)&h[2];
    *(__nv_bfloat162*)&L[o]     = *(__nv_bfloat162*)&l[0];
    *(__nv_bfloat162*)&L[o + 2] = *(__nv_bfloat162*)&l[2];
}

__global__ __launch_bounds__(256) void zero_pk()
{
    int i = blockIdx.x * 256 + threadIdx.x;
    if (i < NB * 9 * 30 * 11) g_pk[i] = 0.f;
}

// ---------------- pool: conv-pattern mma (TM=32, WC=8) + RBF on fragments ----------------
// grid (NB, 9, 2): b, pair, d-chunk of 128. smem: AH 0, AL 4608, BH 9216, BL 27648. 46080 total.
#define PM_AH 0
#define PM_AL 4608
#define PM_BH 9216
#define PM_BL 27648
#define PM_TOT 46080

__global__ __launch_bounds__(256) void poolmma(const float* __restrict__ qmask,
                                               const float* __restrict__ dmask)
{
    extern __shared__ char sm[];
    const uint32_t sbase = smem_u32(sm);

    const int tid  = threadIdx.x;
    const int wid  = tid >> 5;
    const int lane = tid & 31;
    const int nc = wid * 16;                 // WC=8, NWN=16, NFRAG=2, mr=0

    const int b    = blockIdx.x;
    const int pair = blockIdx.y;
    const int z    = blockIdx.z;             // d-chunk
    const int gi = pair / 3;
    const int gt = pair - gi * 3;

    const int lg = lane >> 3, l7 = lane & 7;
    const uint32_t a_off = (((lg & 1) * 8 + l7) * 72 + ((lg >> 1) * 8)) * 2;
    const uint32_t b_off = ((nc + (lg >> 1) * 8 + l7) * 72 + ((lg & 1) * 8)) * 2;

    float acc[2][2][4];
#pragma unroll
    for (int f = 0; f < 2; f++)
#pragma unroll
        for (int j = 0; j < 2; j++)
#pragma unroll
            for (int t = 0; t < 4; t++) acc[f][j][t] = 0.f;

    for (int cc = 0; cc < 2; cc++) {         // K chunks of 64
        const int e0 = cc * 64;
        const __nv_bfloat16* ah = g_Qh2 + ((size_t)b * 32) * 384 + gi * 128 + e0;
        const __nv_bfloat16* al = g_Ql2 + ((size_t)b * 32) * 384 + gi * 128 + e0;
        const __nv_bfloat16* bh = g_Dh2 + ((size_t)(b * ND + z * 128)) * 384 + gt * 128 + e0;
        const __nv_bfloat16* bl = g_Dl2 + ((size_t)(b * ND + z * 128)) * 384 + gt * 128 + e0;

        __syncthreads();
        {   // A: 32 rows x 8 units — exactly 256 threads
            int r = tid >> 3, c = tid & 7;
            *(uint4*)(sm + PM_AH + r * 144 + c * 16) = *(const uint4*)(ah + (size_t)r * 384 + c * 8);
            *(uint4*)(sm + PM_AL + r * 144 + c * 16) = *(const uint4*)(al + (size_t)r * 384 + c * 8);
        }
#pragma unroll
        for (int u = tid; u < 1024; u += 256) {
            int r = u >> 3, c = u & 7;
            *(uint4*)(sm + PM_BH + r * 144 + c * 16) = *(const uint4*)(bh + (size_t)r * 384 + c * 8);
            *(uint4*)(sm + PM_BL + r * 144 + c * 16) = *(const uint4*)(bl + (size_t)r * 384 + c * 8);
        }
        __syncthreads();

#pragma unroll
        for (int ks = 0; ks < 4; ks++) {
            uint32_t ahf[2][4], alf[2][4], bhf[4], blf[4];
            ldsm4(ahf[0], sbase + PM_AH + a_off + ks * 32);
            ldsm4(ahf[1], sbase + PM_AH + a_off + 16 * 144 + ks * 32);
            ldsm4(alf[0], sbase + PM_AL + a_off + ks * 32);
            ldsm4(alf[1], sbase + PM_AL + a_off + 16 * 144 + ks * 32);
            ldsm4(bhf, sbase + PM_BH + b_off + ks * 32);
            ldsm4(blf, sbase + PM_BL + b_off + ks * 32);
#pragma unroll
            for (int f = 0; f < 2; f++)
#pragma unroll
                for (int j = 0; j < 2; j++) {
                    mma16816(acc[f][j], ahf[f], &bhf[j * 2]);
                    mma16816(acc[f][j], ahf[f], &blf[j * 2]);
                    mma16816(acc[f][j], alf[f], &bhf[j * 2]);
                }
        }
    }

    // RBF on fragments; mapping identical to conv epilogue (row = f*16 + h*8 + lq, col = nc + j*8 + 2lr + e)
    const int lq = lane >> 2, lr = lane & 3;
    const float U1 = 0.13533528323661270f;   // e^-2
    const float U2 = 0.018315638888734179f;  // e^-4

    float qacc[4][11];
#pragma unroll
    for (int s = 0; s < 4; s++)
#pragma unroll
        for (int k = 0; k < 11; k++) qacc[s][k] = 0.f;

#pragma unroll
    for (int f = 0; f < 2; f++)
#pragma unroll
        for (int h = 0; h < 2; h++) {
            int row = f * 16 + h * 8 + lq;
            float qmv = (row < NQ) ? __ldg(&qmask[b * NQ + row]) : 0.f;
            int slot = f * 2 + h;
#pragma unroll
            for (int j = 0; j < 2; j++)
#pragma unroll
                for (int e = 0; e < 2; e++) {
                    int col = z * 128 + nc + j * 8 + 2 * lr + e;
                    float m = qmv * __ldg(&dmask[b * ND + col]);
                    float c = acc[f][j][h * 2 + e] * m;
                    float x = c - 0.9f;
                    float e1 = __expf(-50.f * x * x) * m;
                    float t  = __expf(-20.f * x);
                    float t0 = c - 1.0f;
                    qacc[slot][0] += __expf(-500000.f * t0 * t0) * m;
                    float v = e1;
                    qacc[slot][1] += v;
                    float r = t * U1;
#pragma unroll
                    for (int kk = 2; kk < 11; kk++) {
                        v *= r;
                        qacc[slot][kk] += v;
                        r *= U2;
                    }
                }
        }

#pragma unroll
    for (int s = 0; s < 4; s++)
#pragma unroll
        for (int k = 0; k < 11; k++) {
            float v = qacc[s][k];
            v += __shfl_xor_sync(0xffffffffu, v, 1);
            v += __shfl_xor_sync(0xffffffffu, v, 2);
            qacc[s][k] = v;
        }
    if (lr == 0) {
#pragma unroll
        for (int s = 0; s < 4; s++) {
            int row = (s >> 1) * 16 + (s & 1) * 8 + lq;
            if (row < NQ) {
                float* dst = &g_pk[(((size_t)(b * 9 + pair)) * 30 + row) * 11];
#pragma unroll
                for (int k = 0; k < 11; k++) atomicAdd(&dst[k], qacc[s][k]);
            }
        }
    }
}

// ---------------- finish: clip/log/mask/row-sum ----------------
__global__ __launch_bounds__(352) void finish_kernel(const float* __restrict__ qmask)
{
    __shared__ float t[330];
    const int b = blockIdx.x, pair = blockIdx.y, tid = threadIdx.x;
    if (tid < 330) {
        int row = tid / 11;
        float pk = fmaxf(g_pk[(((size_t)(b * 9 + pair)) * 30 + row) * 11 + tid % 11], 1e-10f);
        t[tid] = __logf(pk) * 0.01f * __ldg(&qmask[b * NQ + row]);
    }
    __syncthreads();
    if (tid < 11) {
        float s = 0.f;
#pragma unroll
        for (int q = 0; q < NQ; q++) s += t[q * 11 + tid];
        g_feat[b * 99 + pair * 11 + tid] = s;
    }
}

// ---------------- final dense ----------------
__global__ void final_kernel(const float* __restrict__ dw, float* __restrict__ out)
{
    int b = threadIdx.x;
    if (b < NB) {
        float s = 0.f;
#pragma unroll
        for (int j = 0; j < 99; j++) s += g_feat[b * 99 + j] * dw[j];
        out[b] = s;
    }
}

// ---------------- launch ----------------
extern "C" void kernel_launch(void* const* d_in, const int* in_sizes, int n_in,
                              void* d_out, int out_size)
{
    const float* qe    = (const float*)d_in[0];
    const float* de    = (const float*)d_in[1];
    const float* qmask = (const float*)d_in[2];
    const float* dmask = (const float*)d_in[3];
    const float* w1    = (const float*)d_in[4];
    const float* b1    = (const float*)d_in[5];
    const float* w2    = (const float*)d_in[6];
    const float* b2    = (const float*)d_in[7];
    const float* w3    = (const float*)d_in[8];
    const float* b3    = (const float*)d_in[9];
    const float* dw    = (const float*)d_in[10];
    float* out = (float*)d_out;

    __nv_bfloat16 *xqh, *xql, *xdh, *xdl, *qh2, *ql2, *dh2, *dl2;
    float *qf, *df;
    cudaGetSymbolAddress((void**)&xqh, g_Xqh);
    cudaGetSymbolAddress((void**)&xql, g_Xql);
    cudaGetSymbolAddress((void**)&xdh, g_Xdh);
    cudaGetSymbolAddress((void**)&xdl, g_Xdl);
    cudaGetSymbolAddress((void**)&qh2, g_Qh2);
    cudaGetSymbolAddress((void**)&ql2, g_Ql2);
    cudaGetSymbolAddress((void**)&dh2, g_Dh2);
    cudaGetSymbolAddress((void**)&dl2, g_Dl2);
    cudaGetSymbolAddress((void**)&qf, g_Q);
    cudaGetSymbolAddress((void**)&df, g_D);

    prep_w<<<(245760 + 255) / 256, 256>>>(w1, w2, w3);
    prep_x<XQROWS, NQ><<<(NB * XQROWS * (KP / 4) + 255) / 256, 256>>>(qe, xqh, xql);
    prep_x<XDROWS, ND><<<(NB * XDROWS * (KP / 4) + 255) / 256, 256>>>(de, xdh, xdl);

    const int SMEMD = 2 * 128 * 144 + 2 * 18432 + 128 * 4;
    const int SMEMQ = 2 * 32 * 144 + 2 * 18432 + 128 * 4;
    cudaFuncSetAttribute(convmma<32, 8, XQROWS, NQ, true >, cudaFuncAttributeMaxDynamicSharedMemorySize, SMEMQ);
    cudaFuncSetAttribute(convmma<128, 2, XDROWS, ND, false>, cudaFuncAttributeMaxDynamicSharedMemorySize, SMEMD);
    convmma<32, 8, XQROWS, NQ, true ><<<dim3(1, NB, 3), 256, SMEMQ>>>(b1, b2, b3);
    convmma<128, 2, XDROWS, ND, false><<<dim3(2, NB, 3), 256, SMEMD>>>(b1, b2, b3);

    split_q<<<(NB * 32 * 96 + 255) / 256, 256>>>(qf, qh2, ql2);
    int nd4 = NB * ND * 384 / 4;
    split_hl<<<(nd4 + 255) / 256, 256>>>(df, dh2, dl2, nd4);
    zero_pk<<<(NB * 9 * 30 * 11 + 255) / 256, 256>>>();

    cudaFuncSetAttribute(poolmma, cudaFuncAttributeMaxDynamicSharedMemorySize, PM_TOT);
    poolmma<<<dim3(NB, 9, 2), 256, PM_TOT>>>(qmask, dmask);

    finish_kernel<<<dim3(NB, 9), 352>>>(qmask);
    final_kernel<<<1, 128>>>(dw, out);
}

// round 8
// speedup vs baseline: 4.2697x; 1.0111x over previous
#include <cuda_runtime.h>
#include <cuda_bf16.h>
#include <math.h>
#include <cstdint>

#define NB 128
#define NQ 30
#define ND 256
#define NE 300
#define KP 320
#define XQROWS 34
#define XDROWS 258

// ---------------- scratch ----------------
__device__ __align__(16) __nv_bfloat16 g_Xqh[NB * XQROWS * KP];
__device__ __align__(16) __nv_bfloat16 g_Xql[NB * XQROWS * KP];
__device__ __align__(16) __nv_bfloat16 g_Xdh[NB * XDROWS * KP];
__device__ __align__(16) __nv_bfloat16 g_Xdl[NB * XDROWS * KP];
__device__ __align__(16) __nv_bfloat16 g_Wh[245760];
__device__ __align__(16) __nv_bfloat16 g_Wl[245760];
__device__ __align__(16) __nv_bfloat16 g_Qh2[NB * 32 * 384];   // rows 30,31 stay zero (never written)
__device__ __align__(16) __nv_bfloat16 g_Ql2[NB * 32 * 384];
__device__ __align__(16) __nv_bfloat16 g_Dh2[NB * ND * 384];
__device__ __align__(16) __nv_bfloat16 g_Dl2[NB * ND * 384];
__device__ float g_pk[NB * 9 * 30 * 11];
__device__ float g_feat[NB * 99];

__device__ __forceinline__ uint32_t smem_u32(const void* p) {
    uint32_t a;
    asm("{ .reg .u64 t; cvta.to.shared.u64 t, %1; cvt.u32.u64 %0, t; }" : "=r"(a) : "l"(p));
    return a;
}
__device__ __forceinline__ void ldsm4(uint32_t* r, uint32_t addr) {
    asm volatile("ldmatrix.sync.aligned.m8n8.x4.shared.b16 {%0,%1,%2,%3}, [%4];"
                 : "=r"(r[0]), "=r"(r[1]), "=r"(r[2]), "=r"(r[3]) : "r"(addr));
}
__device__ __forceinline__ void mma16816(float* c, const uint32_t* a, const uint32_t* b) {
    asm volatile("mma.sync.aligned.m16n8k16.row.col.f32.bf16.bf16.f32 "
                 "{%0,%1,%2,%3}, {%4,%5,%6,%7}, {%8,%9}, {%0,%1,%2,%3};"
                 : "+f"(c[0]), "+f"(c[1]), "+f"(c[2]), "+f"(c[3])
                 : "r"(a[0]), "r"(a[1]), "r"(a[2]), "r"(a[3]), "r"(b[0]), "r"(b[1]));
}

// ---------------- prep kernels (proven) ----------------
__global__ __launch_bounds__(256) void prep_w(const float* __restrict__ w1,
                                              const float* __restrict__ w2,
                                              const float* __restrict__ w3)
{
    int idx = blockIdx.x * 256 + threadIdx.x;
    if (idx >= 245760) return;
    int g, base, rs;
    if (idx < 40960)       { g = 0; base = 0;      rs = 320; }
    else if (idx < 122880) { g = 1; base = 40960;  rs = 640; }
    else                   { g = 2; base = 122880; rs = 960; }
    int off = idx - base;
    int n = off / rs;
    int r = off - n * rs;
    int tap = r / KP;
    int e = r - tap * KP;
    float v = 0.f;
    if (e < NE) {
        const float* w = (g == 0) ? w1 : ((g == 1) ? w2 : w3);
        v = w[(n * NE + e) * (g + 1) + tap];
    }
    __nv_bfloat16 h = __float2bfloat16(v);
    g_Wh[idx] = h;
    g_Wl[idx] = __float2bfloat16(v - __bfloat162float(h));
}

template<int ROWS, int LVALID>
__global__ __launch_bounds__(256) void prep_x(const float* __restrict__ X,
                                              __nv_bfloat16* __restrict__ Xh,
                                              __nv_bfloat16* __restrict__ Xl)
{
    int idx = blockIdx.x * 256 + threadIdx.x;
    const int T = NB * ROWS * (KP / 4);
    if (idx >= T) return;
    int e4  = idx % (KP / 4);
    int row = idx / (KP / 4);
    int b = row / ROWS;
    int p = row - b * ROWS;
    int e0 = e4 * 4;
    float4 v = make_float4(0.f, 0.f, 0.f, 0.f);
    if (p < LVALID && e0 < NE)
        v = *(const float4*)&X[((size_t)(b * LVALID + p)) * NE + e0];
    __nv_bfloat16 h[4], l[4];
    float vv[4] = {v.x, v.y, v.z, v.w};
#pragma unroll
    for (int j = 0; j < 4; j++) {
        h[j] = __float2bfloat16(vv[j]);
        l[j] = __float2bfloat16(vv[j] - __bfloat162float(h[j]));
    }
    size_t o = (size_t)row * KP + e0;
    *(__nv_bfloat162*)&Xh[o]     = *(__nv_bfloat162*)&h[0];
    *(__nv_bfloat162*)&Xh[o + 2] = *(__nv_bfloat162*)&h[2];
    *(__nv_bfloat162*)&Xl[o]     = *(__nv_bfloat162*)&l[0];
    *(__nv_bfloat162*)&Xl[o + 2] = *(__nv_bfloat162*)&l[2];
}

// ---------------- conv GEMM via mma.sync (proven mainloop; TM=128, WC=2) ----------------
// IS_Q: 4 batches x 32 rows per block, grid (1, 32, 3). Doc: 128 positions, grid (2, NB, 3).
// Epilogue writes bf16 hi/lo directly (query: 32-row layout; rows>=30 never written -> stay zero).
template<bool IS_Q>
__global__ __launch_bounds__(256) void convmma(const float* __restrict__ bs0,
                                               const float* __restrict__ bs1,
                                               const float* __restrict__ bs2)
{
    constexpr int TM = 128, NFRAG = 8, NJ2 = 4, SA = 72;
    constexpr int AH = 0;
    constexpr int AL = TM * 144;
    constexpr int BH = 2 * TM * 144;
    constexpr int BL = BH + 18432;
    constexpr int SQ = BL + 18432;
    constexpr int XR = IS_Q ? XQROWS : XDROWS;

    extern __shared__ char sm[];
    const uint32_t sbase = smem_u32(sm);

    const int tid  = threadIdx.x;
    const int wid  = tid >> 5;
    const int lane = tid & 31;
    const int wr  = wid >> 1;
    const int wcn = wid & 1;
    const int mr = wr * 32;
    const int nc = wcn * 64;

    const int g  = blockIdx.z;
    const int by = blockIdx.y;
    const int b0 = IS_Q ? by * 4 : by;        // query: batch group; doc: batch
    const int m0 = blockIdx.x * TM;           // doc position tile (query: 0)
    const int wbase = (g == 0) ? 0 : ((g == 1) ? 40960 : 122880);
    const int wrs = (g + 1) * KP;
    const float* bias = (g == 0) ? bs0 : ((g == 1) ? bs1 : bs2);
    const __nv_bfloat16* Xh = IS_Q ? g_Xqh : g_Xdh;
    const __nv_bfloat16* Xl = IS_Q ? g_Xql : g_Xdl;

    if (tid < TM) *(float*)(sm + SQ + tid * 4) = 0.f;

    const int lg = lane >> 3, l7 = lane & 7;
    const uint32_t a_off = ((mr + (lg & 1) * 8 + l7) * SA + ((lg >> 1) * 8)) * 2;
    const uint32_t b_off = ((nc + (lg >> 1) * 8 + l7) * SA + ((lg & 1) * 8)) * 2;

    float acc[2][NFRAG][4];
#pragma unroll
    for (int f = 0; f < 2; f++)
#pragma unroll
        for (int j = 0; j < NFRAG; j++)
#pragma unroll
            for (int t = 0; t < 4; t++) acc[f][j][t] = 0.f;

    const int NCC = 5 * (g + 1);
    for (int cc = 0; cc < NCC; cc++) {
        int tap = cc / 5;
        int e0 = (cc - tap * 5) * 64;
        const __nv_bfloat16* bh = g_Wh + wbase + tap * KP + e0;
        const __nv_bfloat16* bl = g_Wl + wbase + tap * KP + e0;

        __syncthreads();
#pragma unroll
        for (int u = tid; u < TM * 8; u += 256) {
            int r = u >> 3, c = u & 7;
            size_t arow = IS_Q ? ((size_t)(b0 + (r >> 5)) * XR + (r & 31) + tap)
                               : ((size_t)b0 * XR + m0 + r + tap);
            size_t go = arow * KP + e0 + c * 8;
            *(uint4*)(sm + AH + r * 144 + c * 16) = *(const uint4*)(Xh + go);
            *(uint4*)(sm + AL + r * 144 + c * 16) = *(const uint4*)(Xl + go);
        }
#pragma unroll
        for (int u = tid; u < 1024; u += 256) {
            int r = u >> 3, c = u & 7;
            *(uint4*)(sm + BH + r * 144 + c * 16) = *(const uint4*)(bh + (size_t)r * wrs + c * 8);
            *(uint4*)(sm + BL + r * 144 + c * 16) = *(const uint4*)(bl + (size_t)r * wrs + c * 8);
        }
        __syncthreads();

#pragma unroll
        for (int ks = 0; ks < 4; ks++) {
            uint32_t ahf[2][4], alf[2][4];
            ldsm4(ahf[0], sbase + AH + a_off + ks * 32);
            ldsm4(ahf[1], sbase + AH + a_off + 16 * SA * 2 + ks * 32);
            ldsm4(alf[0], sbase + AL + a_off + ks * 32);
            ldsm4(alf[1], sbase + AL + a_off + 16 * SA * 2 + ks * 32);
            uint32_t bhf[NJ2][4], blf[NJ2][4];
#pragma unroll
            for (int j2 = 0; j2 < NJ2; j2++) {
                ldsm4(bhf[j2], sbase + BH + b_off + j2 * 16 * SA * 2 + ks * 32);
                ldsm4(blf[j2], sbase + BL + b_off + j2 * 16 * SA * 2 + ks * 32);
            }
#pragma unroll
            for (int f = 0; f < 2; f++)
#pragma unroll
                for (int j = 0; j < NFRAG; j++) {
                    const uint32_t* bhp = &bhf[j >> 1][(j & 1) * 2];
                    const uint32_t* blp = &blf[j >> 1][(j & 1) * 2];
                    mma16816(acc[f][j], ahf[f], bhp);
                    mma16816(acc[f][j], ahf[f], blp);
                    mma16816(acc[f][j], alf[f], bhp);
                }
        }
    }

    // epilogue: bias + relu + rowwise L2 norm (proven), then direct bf16 hi/lo store
    const int lq = lane >> 2, lr = lane & 3;
    float ssq_p[2][2] = {{0.f, 0.f}, {0.f, 0.f}};
#pragma unroll
    for (int f = 0; f < 2; f++)
#pragma unroll
        for (int j = 0; j < NFRAG; j++) {
            float bv0 = __ldg(&bias[nc + j * 8 + 2 * lr]);
            float bv1 = __ldg(&bias[nc + j * 8 + 2 * lr + 1]);
            float v0 = fmaxf(acc[f][j][0] + bv0, 0.f);
            float v1 = fmaxf(acc[f][j][1] + bv1, 0.f);
            float v2 = fmaxf(acc[f][j][2] + bv0, 0.f);
            float v3 = fmaxf(acc[f][j][3] + bv1, 0.f);
            acc[f][j][0] = v0; acc[f][j][1] = v1; acc[f][j][2] = v2; acc[f][j][3] = v3;
            ssq_p[f][0] += v0 * v0 + v1 * v1;
            ssq_p[f][1] += v2 * v2 + v3 * v3;
        }
#pragma unroll
    for (int f = 0; f < 2; f++)
#pragma unroll
        for (int h = 0; h < 2; h++) {
            float v = ssq_p[f][h];
            v += __shfl_xor_sync(0xffffffffu, v, 1);
            v += __shfl_xor_sync(0xffffffffu, v, 2);
            if (lr == 0)
                atomicAdd((float*)(sm + SQ + (mr + f * 16 + h * 8 + lq) * 4), v);
        }
    __syncthreads();

    __nv_bfloat16* OH = IS_Q ? g_Qh2 : g_Dh2;
    __nv_bfloat16* OL = IS_Q ? g_Ql2 : g_Dl2;
#pragma unroll
    for (int f = 0; f < 2; f++)
#pragma unroll
        for (int h = 0; h < 2; h++) {
            int r = mr + f * 16 + h * 8 + lq;            // block row 0..127
            float inv = 1.f / (sqrtf(*(float*)(sm + SQ + r * 4)) + 1e-13f);
            bool valid;
            size_t orow;
            if (IS_Q) {
                int pos = r & 31;
                valid = pos < NQ;
                orow = (size_t)(b0 + (r >> 5)) * 32 + pos;
            } else {
                valid = true;
                orow = (size_t)b0 * ND + m0 + r;
            }
            if (!valid) continue;
            size_t ob = orow * 384 + g * 128;
#pragma unroll
            for (int j = 0; j < NFRAG; j++) {
                float v0 = acc[f][j][h * 2 + 0] * inv;
                float v1 = acc[f][j][h * 2 + 1] * inv;
                __nv_bfloat16 h0 = __float2bfloat16(v0);
                __nv_bfloat16 h1 = __float2bfloat16(v1);
                __nv_bfloat16 l0 = __float2bfloat16(v0 - __bfloat162float(h0));
                __nv_bfloat16 l1 = __float2bfloat16(v1 - __bfloat162float(h1));
                __nv_bfloat162 ph; ph.x = h0; ph.y = h1;
                __nv_bfloat162 pl; pl.x = l0; pl.y = l1;
                size_t o = ob + nc + j * 8 + 2 * lr;
                *(__nv_bfloat162*)&OH[o] = ph;
                *(__nv_bfloat162*)&OL[o] = pl;
            }
        }
}

__global__ __launch_bounds__(256) void zero_pk()
{
    int i = blockIdx.x * 256 + threadIdx.x;
    if (i < NB * 9 * 30 * 11) g_pk[i] = 0.f;
}

// ---------------- pool: proven round-7 kernel ----------------
#define PM_AH 0
#define PM_AL 4608
#define PM_BH 9216
#define PM_BL 27648
#define PM_TOT 46080

__global__ __launch_bounds__(256) void poolmma(const float* __restrict__ qmask,
                                               const float* __restrict__ dmask)
{
    extern __shared__ char sm[];
    const uint32_t sbase = smem_u32(sm);

    const int tid  = threadIdx.x;
    const int wid  = tid >> 5;
    const int lane = tid & 31;
    const int nc = wid * 16;

    const int b    = blockIdx.x;
    const int pair = blockIdx.y;
    const int z    = blockIdx.z;
    const int gi = pair / 3;
    const int gt = pair - gi * 3;

    const int lg = lane >> 3, l7 = lane & 7;
    const uint32_t a_off = (((lg & 1) * 8 + l7) * 72 + ((lg >> 1) * 8)) * 2;
    const uint32_t b_off = ((nc + (lg >> 1) * 8 + l7) * 72 + ((lg & 1) * 8)) * 2;

    float acc[2][2][4];
#pragma unroll
    for (int f = 0; f < 2; f++)
#pragma unroll
        for (int j = 0; j < 2; j++)
#pragma unroll
            for (int t = 0; t < 4; t++) acc[f][j][t] = 0.f;

    for (int cc = 0; cc < 2; cc++) {
        const int e0 = cc * 64;
        const __nv_bfloat16* ah = g_Qh2 + ((size_t)b * 32) * 384 + gi * 128 + e0;
        const __nv_bfloat16* al = g_Ql2 + ((size_t)b * 32) * 384 + gi * 128 + e0;
        const __nv_bfloat16* bh = g_Dh2 + ((size_t)(b * ND + z * 128)) * 384 + gt * 128 + e0;
        const __nv_bfloat16* bl = g_Dl2 + ((size_t)(b * ND + z * 128)) * 384 + gt * 128 + e0;

        __syncthreads();
        {
            int r = tid >> 3, c = tid & 7;
            *(uint4*)(sm + PM_AH + r * 144 + c * 16) = *(const uint4*)(ah + (size_t)r * 384 + c * 8);
            *(uint4*)(sm + PM_AL + r * 144 + c * 16) = *(const uint4*)(al + (size_t)r * 384 + c * 8);
        }
#pragma unroll
        for (int u = tid; u < 1024; u += 256) {
            int r = u >> 3, c = u & 7;
            *(uint4*)(sm + PM_BH + r * 144 + c * 16) = *(const uint4*)(bh + (size_t)r * 384 + c * 8);
            *(uint4*)(sm + PM_BL + r * 144 + c * 16) = *(const uint4*)(bl + (size_t)r * 384 + c * 8);
        }
        __syncthreads();

#pragma unroll
        for (int ks = 0; ks < 4; ks++) {
            uint32_t ahf[2][4], alf[2][4], bhf[4], blf[4];
            ldsm4(ahf[0], sbase + PM_AH + a_off + ks * 32);
            ldsm4(ahf[1], sbase + PM_AH + a_off + 16 * 144 + ks * 32);
            ldsm4(alf[0], sbase + PM_AL + a_off + ks * 32);
            ldsm4(alf[1], sbase + PM_AL + a_off + 16 * 144 + ks * 32);
            ldsm4(bhf, sbase + PM_BH + b_off + ks * 32);
            ldsm4(blf, sbase + PM_BL + b_off + ks * 32);
#pragma unroll
            for (int f = 0; f < 2; f++)
#pragma unroll
                for (int j = 0; j < 2; j++) {
                    mma16816(acc[f][j], ahf[f], &bhf[j * 2]);
                    mma16816(acc[f][j], ahf[f], &blf[j * 2]);
                    mma16816(acc[f][j], alf[f], &bhf[j * 2]);
                }
        }
    }

    const int lq = lane >> 2, lr = lane & 3;
    const float U1 = 0.13533528323661270f;   // e^-2
    const float U2 = 0.018315638888734179f;  // e^-4

    float qacc[4][11];
#pragma unroll
    for (int s = 0; s < 4; s++)
#pragma unroll
        for (int k = 0; k < 11; k++) qacc[s][k] = 0.f;

#pragma unroll
    for (int f = 0; f < 2; f++)
#pragma unroll
        for (int h = 0; h < 2; h++) {
            int row = f * 16 + h * 8 + lq;
            float qmv = (row < NQ) ? __ldg(&qmask[b * NQ + row]) : 0.f;
            int slot = f * 2 + h;
#pragma unroll
            for (int j = 0; j < 2; j++)
#pragma unroll
                for (int e = 0; e < 2; e++) {
                    int col = z * 128 + nc + j * 8 + 2 * lr + e;
                    float m = qmv * __ldg(&dmask[b * ND + col]);
                    float c = acc[f][j][h * 2 + e] * m;
                    float x = c - 0.9f;
                    float e1 = __expf(-50.f * x * x) * m;
                    float t  = __expf(-20.f * x);
                    float t0 = c - 1.0f;
                    qacc[slot][0] += __expf(-500000.f * t0 * t0) * m;
                    float v = e1;
                    qacc[slot][1] += v;
                    float r = t * U1;
#pragma unroll
                    for (int kk = 2; kk < 11; kk++) {
                        v *= r;
                        qacc[slot][kk] += v;
                        r *= U2;
                    }
                }
        }

#pragma unroll
    for (int s = 0; s < 4; s++)
#pragma unroll
        for (int k = 0; k < 11; k++) {
            float v = qacc[s][k];
            v += __shfl_xor_sync(0xffffffffu, v, 1);
            v += __shfl_xor_sync(0xffffffffu, v, 2);
            qacc[s][k] = v;
        }
    if (lr == 0) {
#pragma unroll
        for (int s = 0; s < 4; s++) {
            int row = (s >> 1) * 16 + (s & 1) * 8 + lq;
            if (row < NQ) {
                float* dst = &g_pk[(((size_t)(b * 9 + pair)) * 30 + row) * 11];
#pragma unroll
                for (int k = 0; k < 11; k++) atomicAdd(&dst[k], qacc[s][k]);
            }
        }
    }
}

// ---------------- finish ----------------
__global__ __launch_bounds__(352) void finish_kernel(const float* __restrict__ qmask)
{
    __shared__ float t[330];
    const int b = blockIdx.x, pair = blockIdx.y, tid = threadIdx.x;
    if (tid < 330) {
        int row = tid / 11;
        float pk = fmaxf(g_pk[(((size_t)(b * 9 + pair)) * 30 + row) * 11 + tid % 11], 1e-10f);
        t[tid] = __logf(pk) * 0.01f * __ldg(&qmask[b * NQ + row]);
    }
    __syncthreads();
    if (tid < 11) {
        float s = 0.f;
#pragma unroll
        for (int q = 0; q < NQ; q++) s += t[q * 11 + tid];
        g_feat[b * 99 + pair * 11 + tid] = s;
    }
}

__global__ void final_kernel(const float* __restrict__ dw, float* __restrict__ out)
{
    int b = threadIdx.x;
    if (b < NB) {
        float s = 0.f;
#pragma unroll
        for (int j = 0; j < 99; j++) s += g_feat[b * 99 + j] * dw[j];
        out[b] = s;
    }
}

// ---------------- launch ----------------
extern "C" void kernel_launch(void* const* d_in, const int* in_sizes, int n_in,
                              void* d_out, int out_size)
{
    const float* qe    = (const float*)d_in[0];
    const float* de    = (const float*)d_in[1];
    const float* qmask = (const float*)d_in[2];
    const float* dmask = (const float*)d_in[3];
    const float* w1    = (const float*)d_in[4];
    const float* b1    = (const float*)d_in[5];
    const float* w2    = (const float*)d_in[6];
    const float* b2    = (const float*)d_in[7];
    const float* w3    = (const float*)d_in[8];
    const float* b3    = (const float*)d_in[9];
    const float* dw    = (const float*)d_in[10];
    float* out = (float*)d_out;

    __nv_bfloat16 *xqh, *xql, *xdh, *xdl;
    cudaGetSymbolAddress((void**)&xqh, g_Xqh);
    cudaGetSymbolAddress((void**)&xql, g_Xql);
    cudaGetSymbolAddress((void**)&xdh, g_Xdh);
    cudaGetSymbolAddress((void**)&xdl, g_Xdl);

    prep_w<<<(245760 + 255) / 256, 256>>>(w1, w2, w3);
    prep_x<XQROWS, NQ><<<(NB * XQROWS * (KP / 4) + 255) / 256, 256>>>(qe, xqh, xql);
    prep_x<XDROWS, ND><<<(NB * XDROWS * (KP / 4) + 255) / 256, 256>>>(de, xdh, xdl);

    const int SMEM = 2 * 128 * 144 + 2 * 18432 + 128 * 4;
    cudaFuncSetAttribute(convmma<true >, cudaFuncAttributeMaxDynamicSharedMemorySize, SMEM);
    cudaFuncSetAttribute(convmma<false>, cudaFuncAttributeMaxDynamicSharedMemorySize, SMEM);
    convmma<true ><<<dim3(1, 32, 3), 256, SMEM>>>(b1, b2, b3);
    convmma<false><<<dim3(2, NB, 3), 256, SMEM>>>(b1, b2, b3);

    zero_pk<<<(NB * 9 * 30 * 11 + 255) / 256, 256>>>();

    cudaFuncSetAttribute(poolmma, cudaFuncAttributeMaxDynamicSharedMemorySize, PM_TOT);
    poolmma<<<dim3(NB, 9, 2), 256, PM_TOT>>>(qmask, dmask);

    finish_kernel<<<dim3(NB, 9), 352>>>(qmask);
    final_kernel<<<1, 128>>>(dw, out);
}

// round 9
// speedup vs baseline: 4.6222x; 1.0826x over previous
#include <cuda_runtime.h>
#include <cuda_bf16.h>
#include <math.h>
#include <cstdint>

#define NB 128
#define NQ 30
#define ND 256
#define NE 300
#define KP 320
#define XQROWS 34
#define XDROWS 258

// ---------------- scratch ----------------
__device__ __align__(16) __nv_bfloat16 g_Xqh[NB * XQROWS * KP];
__device__ __align__(16) __nv_bfloat16 g_Xql[NB * XQROWS * KP];
__device__ __align__(16) __nv_bfloat16 g_Xdh[NB * XDROWS * KP];
__device__ __align__(16) __nv_bfloat16 g_Xdl[NB * XDROWS * KP];
__device__ __align__(16) __nv_bfloat16 g_Wh[245760];
__device__ __align__(16) __nv_bfloat16 g_Wl[245760];
__device__ __align__(16) __nv_bfloat16 g_Qh2[NB * 32 * 384];   // rows 30,31 stay zero
__device__ __align__(16) __nv_bfloat16 g_Ql2[NB * 32 * 384];
__device__ __align__(16) __nv_bfloat16 g_Dh2[NB * ND * 384];
__device__ __align__(16) __nv_bfloat16 g_Dl2[NB * ND * 384];
__device__ float g_pk[NB * 9 * 30 * 11];
__device__ float g_feat[NB * 99];

__device__ __forceinline__ uint32_t smem_u32(const void* p) {
    uint32_t a;
    asm("{ .reg .u64 t; cvta.to.shared.u64 t, %1; cvt.u32.u64 %0, t; }" : "=r"(a) : "l"(p));
    return a;
}
__device__ __forceinline__ void ldsm4(uint32_t* r, uint32_t addr) {
    asm volatile("ldmatrix.sync.aligned.m8n8.x4.shared.b16 {%0,%1,%2,%3}, [%4];"
                 : "=r"(r[0]), "=r"(r[1]), "=r"(r[2]), "=r"(r[3]) : "r"(addr));
}
__device__ __forceinline__ void mma16816(float* c, const uint32_t* a, const uint32_t* b) {
    asm volatile("mma.sync.aligned.m16n8k16.row.col.f32.bf16.bf16.f32 "
                 "{%0,%1,%2,%3}, {%4,%5,%6,%7}, {%8,%9}, {%0,%1,%2,%3};"
                 : "+f"(c[0]), "+f"(c[1]), "+f"(c[2]), "+f"(c[3])
                 : "r"(a[0]), "r"(a[1]), "r"(a[2]), "r"(a[3]), "r"(b[0]), "r"(b[1]));
}
__device__ __forceinline__ void cpa16(uint32_t dst, const void* src) {
    asm volatile("cp.async.ca.shared.global [%0], [%1], 16;" :: "r"(dst), "l"(src) : "memory");
}
#define CP_COMMIT() asm volatile("cp.async.commit_group;" ::: "memory")
#define CP_WAIT(n)  asm volatile("cp.async.wait_group %0;" :: "n"(n) : "memory")

// ---------------- prep kernels (proven) ----------------
__global__ __launch_bounds__(256) void prep_w(const float* __restrict__ w1,
                                              const float* __restrict__ w2,
                                              const float* __restrict__ w3)
{
    int idx = blockIdx.x * 256 + threadIdx.x;
    if (idx >= 245760) return;
    int g, base, rs;
    if (idx < 40960)       { g = 0; base = 0;      rs = 320; }
    else if (idx < 122880) { g = 1; base = 40960;  rs = 640; }
    else                   { g = 2; base = 122880; rs = 960; }
    int off = idx - base;
    int n = off / rs;
    int r = off - n * rs;
    int tap = r / KP;
    int e = r - tap * KP;
    float v = 0.f;
    if (e < NE) {
        const float* w = (g == 0) ? w1 : ((g == 1) ? w2 : w3);
        v = w[(n * NE + e) * (g + 1) + tap];
    }
    __nv_bfloat16 h = __float2bfloat16(v);
    g_Wh[idx] = h;
    g_Wl[idx] = __float2bfloat16(v - __bfloat162float(h));
}

template<int ROWS, int LVALID>
__global__ __launch_bounds__(256) void prep_x(const float* __restrict__ X,
                                              __nv_bfloat16* __restrict__ Xh,
                                              __nv_bfloat16* __restrict__ Xl)
{
    int idx = blockIdx.x * 256 + threadIdx.x;
    const int T = NB * ROWS * (KP / 4);
    if (idx >= T) return;
    int e4  = idx % (KP / 4);
    int row = idx / (KP / 4);
    int b = row / ROWS;
    int p = row - b * ROWS;
    int e0 = e4 * 4;
    float4 v = make_float4(0.f, 0.f, 0.f, 0.f);
    if (p < LVALID && e0 < NE)
        v = *(const float4*)&X[((size_t)(b * LVALID + p)) * NE + e0];
    __nv_bfloat16 h[4], l[4];
    float vv[4] = {v.x, v.y, v.z, v.w};
#pragma unroll
    for (int j = 0; j < 4; j++) {
        h[j] = __float2bfloat16(vv[j]);
        l[j] = __float2bfloat16(vv[j] - __bfloat162float(h[j]));
    }
    size_t o = (size_t)row * KP + e0;
    *(__nv_bfloat162*)&Xh[o]     = *(__nv_bfloat162*)&h[0];
    *(__nv_bfloat162*)&Xh[o + 2] = *(__nv_bfloat162*)&h[2];
    *(__nv_bfloat162*)&Xl[o]     = *(__nv_bfloat162*)&l[0];
    *(__nv_bfloat162*)&Xl[o + 2] = *(__nv_bfloat162*)&l[2];
}

// ---------------- conv GEMM: proven compute + cp.async 3-stage pipeline ----------------
// Stage layout (bytes): AH 0, AL 18432, BH 36864, BL 55296. Stage size 73728, 3 stages.
#define S_AH 0
#define S_AL 18432
#define S_BH 36864
#define S_BL 55296
#define C_STG 73728
#define C_SQ  (3 * C_STG)
#define C_TOT (C_SQ + 512)

template<bool IS_Q>
__global__ __launch_bounds__(256) void convmma(const float* __restrict__ bs0,
                                               const float* __restrict__ bs1,
                                               const float* __restrict__ bs2)
{
    constexpr int TM = 128, NFRAG = 8, NJ2 = 4, SA = 72;
    constexpr int XR = IS_Q ? XQROWS : XDROWS;

    extern __shared__ char sm[];
    const uint32_t sbase = smem_u32(sm);

    const int tid  = threadIdx.x;
    const int wid  = tid >> 5;
    const int lane = tid & 31;
    const int wr  = wid >> 1;
    const int wcn = wid & 1;
    const int mr = wr * 32;
    const int nc = wcn * 64;

    const int g  = blockIdx.z;
    const int by = blockIdx.y;
    const int b0 = IS_Q ? by * 4 : by;
    const int m0 = blockIdx.x * TM;
    const int wbase = (g == 0) ? 0 : ((g == 1) ? 40960 : 122880);
    const int wrs = (g + 1) * KP;
    const float* bias = (g == 0) ? bs0 : ((g == 1) ? bs1 : bs2);
    const __nv_bfloat16* Xh = IS_Q ? g_Xqh : g_Xdh;
    const __nv_bfloat16* Xl = IS_Q ? g_Xql : g_Xdl;

    if (tid < TM) *(float*)(sm + C_SQ + tid * 4) = 0.f;

    const int lg = lane >> 3, l7 = lane & 7;
    const uint32_t a_off = ((mr + (lg & 1) * 8 + l7) * SA + ((lg >> 1) * 8)) * 2;
    const uint32_t b_off = ((nc + (lg >> 1) * 8 + l7) * SA + ((lg & 1) * 8)) * 2;

    float acc[2][NFRAG][4];
#pragma unroll
    for (int f = 0; f < 2; f++)
#pragma unroll
        for (int j = 0; j < NFRAG; j++)
#pragma unroll
            for (int t = 0; t < 4; t++) acc[f][j][t] = 0.f;

    const int NCC = 5 * (g + 1);

    // cp.async stage loader: chunk s -> stage s%3
    auto load_stage = [&](int s) {
        uint32_t sb = sbase + (uint32_t)(s % 3) * C_STG;
        int tap = s / 5;
        int e0 = (s - tap * 5) * 64;
        const __nv_bfloat16* bh = g_Wh + wbase + tap * KP + e0;
        const __nv_bfloat16* bl = g_Wl + wbase + tap * KP + e0;
#pragma unroll
        for (int it = 0; it < 4; it++) {
            int u = tid + it * 256;
            int r = u >> 3, c = u & 7;
            size_t arow = IS_Q ? ((size_t)(b0 + (r >> 5)) * XR + (r & 31) + tap)
                               : ((size_t)b0 * XR + m0 + r + tap);
            size_t go = arow * KP + e0 + c * 8;
            uint32_t dof = r * 144 + c * 16;
            cpa16(sb + S_AH + dof, Xh + go);
            cpa16(sb + S_AL + dof, Xl + go);
            size_t wo = (size_t)r * wrs + e0 + c * 8;  // bh/bl already include tap*KP
            cpa16(sb + S_BH + dof, g_Wh + wbase + tap * KP + wo - e0 + e0);  // placeholder removed below
            cpa16(sb + S_BL + dof, bl + (size_t)r * wrs + c * 8);
        }
    };
    // NOTE: simplify B-hi addressing (the lambda above had a redundant expression);
    // re-define cleanly:
    auto load_stage2 = [&](int s) {
        uint32_t sb = sbase + (uint32_t)(s % 3) * C_STG;
        int tap = s / 5;
        int e0 = (s - tap * 5) * 64;
        const __nv_bfloat16* bh = g_Wh + wbase + tap * KP + e0;
        const __nv_bfloat16* bl = g_Wl + wbase + tap * KP + e0;
#pragma unroll
        for (int it = 0; it < 4; it++) {
            int u = tid + it * 256;
            int r = u >> 3, c = u & 7;
            size_t arow = IS_Q ? ((size_t)(b0 + (r >> 5)) * XR + (r & 31) + tap)
                               : ((size_t)b0 * XR + m0 + r + tap);
            size_t go = arow * KP + e0 + c * 8;
            uint32_t dof = r * 144 + c * 16;
            cpa16(sb + S_AH + dof, Xh + go);
            cpa16(sb + S_AL + dof, Xl + go);
            cpa16(sb + S_BH + dof, bh + (size_t)r * wrs + c * 8);
            cpa16(sb + S_BL + dof, bl + (size_t)r * wrs + c * 8);
        }
    };
    (void)load_stage;

    load_stage2(0);
    CP_COMMIT();

    for (int cc = 0; cc < NCC; cc++) {
        if (cc + 1 < NCC) { load_stage2(cc + 1); CP_COMMIT(); }
        if (cc + 1 < NCC) CP_WAIT(1); else CP_WAIT(0);
        __syncthreads();

        const uint32_t sb = sbase + (uint32_t)(cc % 3) * C_STG;
#pragma unroll
        for (int ks = 0; ks < 4; ks++) {
            uint32_t ahf[2][4], alf[2][4];
            ldsm4(ahf[0], sb + S_AH + a_off + ks * 32);
            ldsm4(ahf[1], sb + S_AH + a_off + 16 * SA * 2 + ks * 32);
            ldsm4(alf[0], sb + S_AL + a_off + ks * 32);
            ldsm4(alf[1], sb + S_AL + a_off + 16 * SA * 2 + ks * 32);
            uint32_t bhf[NJ2][4], blf[NJ2][4];
#pragma unroll
            for (int j2 = 0; j2 < NJ2; j2++) {
                ldsm4(bhf[j2], sb + S_BH + b_off + j2 * 16 * SA * 2 + ks * 32);
                ldsm4(blf[j2], sb + S_BL + b_off + j2 * 16 * SA * 2 + ks * 32);
            }
#pragma unroll
            for (int f = 0; f < 2; f++)
#pragma unroll
                for (int j = 0; j < NFRAG; j++) {
                    const uint32_t* bhp = &bhf[j >> 1][(j & 1) * 2];
                    const uint32_t* blp = &blf[j >> 1][(j & 1) * 2];
                    mma16816(acc[f][j], ahf[f], bhp);
                    mma16816(acc[f][j], ahf[f], blp);
                    mma16816(acc[f][j], alf[f], bhp);
                }
        }
    }

    // epilogue: bias + relu + rowwise L2 norm (proven), direct bf16 hi/lo store
    const int lq = lane >> 2, lr = lane & 3;
    float ssq_p[2][2] = {{0.f, 0.f}, {0.f, 0.f}};
#pragma unroll
    for (int f = 0; f < 2; f++)
#pragma unroll
        for (int j = 0; j < NFRAG; j++) {
            float bv0 = __ldg(&bias[nc + j * 8 + 2 * lr]);
            float bv1 = __ldg(&bias[nc + j * 8 + 2 * lr + 1]);
            float v0 = fmaxf(acc[f][j][0] + bv0, 0.f);
            float v1 = fmaxf(acc[f][j][1] + bv1, 0.f);
            float v2 = fmaxf(acc[f][j][2] + bv0, 0.f);
            float v3 = fmaxf(acc[f][j][3] + bv1, 0.f);
            acc[f][j][0] = v0; acc[f][j][1] = v1; acc[f][j][2] = v2; acc[f][j][3] = v3;
            ssq_p[f][0] += v0 * v0 + v1 * v1;
            ssq_p[f][1] += v2 * v2 + v3 * v3;
        }
    __syncthreads();
#pragma unroll
    for (int f = 0; f < 2; f++)
#pragma unroll
        for (int h = 0; h < 2; h++) {
            float v = ssq_p[f][h];
            v += __shfl_xor_sync(0xffffffffu, v, 1);
            v += __shfl_xor_sync(0xffffffffu, v, 2);
            if (lr == 0)
                atomicAdd((float*)(sm + C_SQ + (mr + f * 16 + h * 8 + lq) * 4), v);
        }
    __syncthreads();

    __nv_bfloat16* OH = IS_Q ? g_Qh2 : g_Dh2;
    __nv_bfloat16* OL = IS_Q ? g_Ql2 : g_Dl2;
#pragma unroll
    for (int f = 0; f < 2; f++)
#pragma unroll
        for (int h = 0; h < 2; h++) {
            int r = mr + f * 16 + h * 8 + lq;
            float inv = 1.f / (sqrtf(*(float*)(sm + C_SQ + r * 4)) + 1e-13f);
            bool valid;
            size_t orow;
            if (IS_Q) {
                int pos = r & 31;
                valid = pos < NQ;
                orow = (size_t)(b0 + (r >> 5)) * 32 + pos;
            } else {
                valid = true;
                orow = (size_t)b0 * ND + m0 + r;
            }
            if (!valid) continue;
            size_t ob = orow * 384 + g * 128;
#pragma unroll
            for (int j = 0; j < NFRAG; j++) {
                float v0 = acc[f][j][h * 2 + 0] * inv;
                float v1 = acc[f][j][h * 2 + 1] * inv;
                __nv_bfloat16 h0 = __float2bfloat16(v0);
                __nv_bfloat16 h1 = __float2bfloat16(v1);
                __nv_bfloat16 l0 = __float2bfloat16(v0 - __bfloat162float(h0));
                __nv_bfloat16 l1 = __float2bfloat16(v1 - __bfloat162float(h1));
                __nv_bfloat162 ph; ph.x = h0; ph.y = h1;
                __nv_bfloat162 pl; pl.x = l0; pl.y = l1;
                size_t o = ob + nc + j * 8 + 2 * lr;
                *(__nv_bfloat162*)&OH[o] = ph;
                *(__nv_bfloat162*)&OL[o] = pl;
            }
        }
}

__global__ __launch_bounds__(256) void zero_pk()
{
    int i = blockIdx.x * 256 + threadIdx.x;
    if (i < NB * 9 * 30 * 11) g_pk[i] = 0.f;
}

// ---------------- pool: proven round-7 kernel (unchanged) ----------------
#define PM_AH 0
#define PM_AL 4608
#define PM_BH 9216
#define PM_BL 27648
#define PM_TOT 46080

__global__ __launch_bounds__(256) void poolmma(const float* __restrict__ qmask,
                                               const float* __restrict__ dmask)
{
    extern __shared__ char sm[];
    const uint32_t sbase = smem_u32(sm);

    const int tid  = threadIdx.x;
    const int wid  = tid >> 5;
    const int lane = tid & 31;
    const int nc = wid * 16;

    const int b    = blockIdx.x;
    const int pair = blockIdx.y;
    const int z    = blockIdx.z;
    const int gi = pair / 3;
    const int gt = pair - gi * 3;

    const int lg = lane >> 3, l7 = lane & 7;
    const uint32_t a_off = (((lg & 1) * 8 + l7) * 72 + ((lg >> 1) * 8)) * 2;
    const uint32_t b_off = ((nc + (lg >> 1) * 8 + l7) * 72 + ((lg & 1) * 8)) * 2;

    float acc[2][2][4];
#pragma unroll
    for (int f = 0; f < 2; f++)
#pragma unroll
        for (int j = 0; j < 2; j++)
#pragma unroll
            for (int t = 0; t < 4; t++) acc[f][j][t] = 0.f;

    for (int cc = 0; cc < 2; cc++) {
        const int e0 = cc * 64;
        const __nv_bfloat16* ah = g_Qh2 + ((size_t)b * 32) * 384 + gi * 128 + e0;
        const __nv_bfloat16* al = g_Ql2 + ((size_t)b * 32) * 384 + gi * 128 + e0;
        const __nv_bfloat16* bh = g_Dh2 + ((size_t)(b * ND + z * 128)) * 384 + gt * 128 + e0;
        const __nv_bfloat16* bl = g_Dl2 + ((size_t)(b * ND + z * 128)) * 384 + gt * 128 + e0;

        __syncthreads();
        {
            int r = tid >> 3, c = tid & 7;
            *(uint4*)(sm + PM_AH + r * 144 + c * 16) = *(const uint4*)(ah + (size_t)r * 384 + c * 8);
            *(uint4*)(sm + PM_AL + r * 144 + c * 16) = *(const uint4*)(al + (size_t)r * 384 + c * 8);
        }
#pragma unroll
        for (int u = tid; u < 1024; u += 256) {
            int r = u >> 3, c = u & 7;
            *(uint4*)(sm + PM_BH + r * 144 + c * 16) = *(const uint4*)(bh + (size_t)r * 384 + c * 8);
            *(uint4*)(sm + PM_BL + r * 144 + c * 16) = *(const uint4*)(bl + (size_t)r * 384 + c * 8);
        }
        __syncthreads();

#pragma unroll
        for (int ks = 0; ks < 4; ks++) {
            uint32_t ahf[2][4], alf[2][4], bhf[4], blf[4];
            ldsm4(ahf[0], sbase + PM_AH + a_off + ks * 32);
            ldsm4(ahf[1], sbase + PM_AH + a_off + 16 * 144 + ks * 32);
            ldsm4(alf[0], sbase + PM_AL + a_off + ks * 32);
            ldsm4(alf[1], sbase + PM_AL + a_off + 16 * 144 + ks * 32);
            ldsm4(bhf, sbase + PM_BH + b_off + ks * 32);
            ldsm4(blf, sbase + PM_BL + b_off + ks * 32);
#pragma unroll
            for (int f = 0; f < 2; f++)
#pragma unroll
                for (int j = 0; j < 2; j++) {
                    mma16816(acc[f][j], ahf[f], &bhf[j * 2]);
                    mma16816(acc[f][j], ahf[f], &blf[j * 2]);
                    mma16816(acc[f][j], alf[f], &bhf[j * 2]);
                }
        }
    }

    const int lq = lane >> 2, lr = lane & 3;
    const float U1 = 0.13533528323661270f;   // e^-2
    const float U2 = 0.018315638888734179f;  // e^-4

    float qacc[4][11];
#pragma unroll
    for (int s = 0; s < 4; s++)
#pragma unroll
        for (int k = 0; k < 11; k++) qacc[s][k] = 0.f;

#pragma unroll
    for (int f = 0; f < 2; f++)
#pragma unroll
        for (int h = 0; h < 2; h++) {
            int row = f * 16 + h * 8 + lq;
            float qmv = (row < NQ) ? __ldg(&qmask[b * NQ + row]) : 0.f;
            int slot = f * 2 + h;
#pragma unroll
            for (int j = 0; j < 2; j++)
#pragma unroll
                for (int e = 0; e < 2; e++) {
                    int col = z * 128 + nc + j * 8 + 2 * lr + e;
                    float m = qmv * __ldg(&dmask[b * ND + col]);
                    float c = acc[f][j][h * 2 + e] * m;
                    float x = c - 0.9f;
                    float e1 = __expf(-50.f * x * x) * m;
                    float t  = __expf(-20.f * x);
                    float t0 = c - 1.0f;
                    qacc[slot][0] += __expf(-500000.f * t0 * t0) * m;
                    float v = e1;
                    qacc[slot][1] += v;
                    float r = t * U1;
#pragma unroll
                    for (int kk = 2; kk < 11; kk++) {
                        v *= r;
                        qacc[slot][kk] += v;
                        r *= U2;
                    }
                }
        }

#pragma unroll
    for (int s = 0; s < 4; s++)
#pragma unroll
        for (int k = 0; k < 11; k++) {
            float v = qacc[s][k];
            v += __shfl_xor_sync(0xffffffffu, v, 1);
            v += __shfl_xor_sync(0xffffffffu, v, 2);
            qacc[s][k] = v;
        }
    if (lr == 0) {
#pragma unroll
        for (int s = 0; s < 4; s++) {
            int row = (s >> 1) * 16 + (s & 1) * 8 + lq;
            if (row < NQ) {
                float* dst = &g_pk[(((size_t)(b * 9 + pair)) * 30 + row) * 11];
#pragma unroll
                for (int k = 0; k < 11; k++) atomicAdd(&dst[k], qacc[s][k]);
            }
        }
    }
}

// ---------------- finish ----------------
__global__ __launch_bounds__(352) void finish_kernel(const float* __restrict__ qmask)
{
    __shared__ float t[330];
    const int b = blockIdx.x, pair = blockIdx.y, tid = threadIdx.x;
    if (tid < 330) {
        int row = tid / 11;
        float pk = fmaxf(g_pk[(((size_t)(b * 9 + pair)) * 30 + row) * 11 + tid % 11], 1e-10f);
        t[tid] = __logf(pk) * 0.01f * __ldg(&qmask[b * NQ + row]);
    }
    __syncthreads();
    if (tid < 11) {
        float s = 0.f;
#pragma unroll
        for (int q = 0; q < NQ; q++) s += t[q * 11 + tid];
        g_feat[b * 99 + pair * 11 + tid] = s;
    }
}

__global__ void final_kernel(const float* __restrict__ dw, float* __restrict__ out)
{
    int b = threadIdx.x;
    if (b < NB) {
        float s = 0.f;
#pragma unroll
        for (int j = 0; j < 99; j++) s += g_feat[b * 99 + j] * dw[j];
        out[b] = s;
    }
}

// ---------------- launch ----------------
extern "C" void kernel_launch(void* const* d_in, const int* in_sizes, int n_in,
                              void* d_out, int out_size)
{
    const float* qe    = (const float*)d_in[0];
    const float* de    = (const float*)d_in[1];
    const float* qmask = (const float*)d_in[2];
    const float* dmask = (const float*)d_in[3];
    const float* w1    = (const float*)d_in[4];
    const float* b1    = (const float*)d_in[5];
    const float* w2    = (const float*)d_in[6];
    const float* b2    = (const float*)d_in[7];
    const float* w3    = (const float*)d_in[8];
    const float* b3    = (const float*)d_in[9];
    const float* dw    = (const float*)d_in[10];
    float* out = (float*)d_out;

    __nv_bfloat16 *xqh, *xql, *xdh, *xdl;
    cudaGetSymbolAddress((void**)&xqh, g_Xqh);
    cudaGetSymbolAddress((void**)&xql, g_Xql);
    cudaGetSymbolAddress((void**)&xdh, g_Xdh);
    cudaGetSymbolAddress((void**)&xdl, g_Xdl);

    prep_w<<<(245760 + 255) / 256, 256>>>(w1, w2, w3);
    prep_x<XQROWS, NQ><<<(NB * XQROWS * (KP / 4) + 255) / 256, 256>>>(qe, xqh, xql);
    prep_x<XDROWS, ND><<<(NB * XDROWS * (KP / 4) + 255) / 256, 256>>>(de, xdh, xdl);

    cudaFuncSetAttribute(convmma<true >, cudaFuncAttributeMaxDynamicSharedMemorySize, C_TOT);
    cudaFuncSetAttribute(convmma<false>, cudaFuncAttributeMaxDynamicSharedMemorySize, C_TOT);
    convmma<true ><<<dim3(1, 32, 3), 256, C_TOT>>>(b1, b2, b3);
    convmma<false><<<dim3(2, NB, 3), 256, C_TOT>>>(b1, b2, b3);

    zero_pk<<<(NB * 9 * 30 * 11 + 255) / 256, 256>>>();

    cudaFuncSetAttribute(poolmma, cudaFuncAttributeMaxDynamicSharedMemorySize, PM_TOT);
    poolmma<<<dim3(NB, 9, 2), 256, PM_TOT>>>(qmask, dmask);

    finish_kernel<<<dim3(NB, 9), 352>>>(qmask);
    final_kernel<<<1, 128>>>(dw, out);
}

// round 10
// speedup vs baseline: 5.0914x; 1.1015x over previous
#include <cuda_runtime.h>
#include <cuda_bf16.h>
#include <math.h>
#include <cstdint>

#define NB 128
#define NQ 30
#define ND 256
#define NE 300
#define KP 320
#define XQROWS 34
#define XDROWS 258

// ---------------- scratch ----------------
__device__ __align__(16) __nv_bfloat16 g_Xqh[NB * XQROWS * KP];
__device__ __align__(16) __nv_bfloat16 g_Xql[NB * XQROWS * KP];
__device__ __align__(16) __nv_bfloat16 g_Xdh[NB * XDROWS * KP];
__device__ __align__(16) __nv_bfloat16 g_Xdl[NB * XDROWS * KP];
__device__ __align__(16) __nv_bfloat16 g_Wh[245760];
__device__ __align__(16) __nv_bfloat16 g_Wl[245760];
__device__ __align__(16) __nv_bfloat16 g_Qh2[NB * 32 * 384];   // rows 30,31 stay zero
__device__ __align__(16) __nv_bfloat16 g_Ql2[NB * 32 * 384];
__device__ __align__(16) __nv_bfloat16 g_Dh2[NB * ND * 384];
__device__ __align__(16) __nv_bfloat16 g_Dl2[NB * ND * 384];
__device__ float g_pk[NB * 9 * 30 * 11];
__device__ float g_feat[NB * 99];

__device__ __forceinline__ uint32_t smem_u32(const void* p) {
    uint32_t a;
    asm("{ .reg .u64 t; cvta.to.shared.u64 t, %1; cvt.u32.u64 %0, t; }" : "=r"(a) : "l"(p));
    return a;
}
__device__ __forceinline__ void ldsm4(uint32_t* r, uint32_t addr) {
    asm volatile("ldmatrix.sync.aligned.m8n8.x4.shared.b16 {%0,%1,%2,%3}, [%4];"
                 : "=r"(r[0]), "=r"(r[1]), "=r"(r[2]), "=r"(r[3]) : "r"(addr));
}
__device__ __forceinline__ void mma16816(float* c, const uint32_t* a, const uint32_t* b) {
    asm volatile("mma.sync.aligned.m16n8k16.row.col.f32.bf16.bf16.f32 "
                 "{%0,%1,%2,%3}, {%4,%5,%6,%7}, {%8,%9}, {%0,%1,%2,%3};"
                 : "+f"(c[0]), "+f"(c[1]), "+f"(c[2]), "+f"(c[3])
                 : "r"(a[0]), "r"(a[1]), "r"(a[2]), "r"(a[3]), "r"(b[0]), "r"(b[1]));
}
__device__ __forceinline__ void cpa16(uint32_t dst, const void* src) {
    asm volatile("cp.async.ca.shared.global [%0], [%1], 16;" :: "r"(dst), "l"(src) : "memory");
}
#define CP_COMMIT() asm volatile("cp.async.commit_group;" ::: "memory")
#define CP_WAIT(n)  asm volatile("cp.async.wait_group %0;" :: "n"(n) : "memory")

// ---------------- prep kernels (proven) ----------------
__global__ __launch_bounds__(256) void prep_w(const float* __restrict__ w1,
                                              const float* __restrict__ w2,
                                              const float* __restrict__ w3)
{
    int idx = blockIdx.x * 256 + threadIdx.x;
    if (idx >= 245760) return;
    int g, base, rs;
    if (idx < 40960)       { g = 0; base = 0;      rs = 320; }
    else if (idx < 122880) { g = 1; base = 40960;  rs = 640; }
    else                   { g = 2; base = 122880; rs = 960; }
    int off = idx - base;
    int n = off / rs;
    int r = off - n * rs;
    int tap = r / KP;
    int e = r - tap * KP;
    float v = 0.f;
    if (e < NE) {
        const float* w = (g == 0) ? w1 : ((g == 1) ? w2 : w3);
        v = w[(n * NE + e) * (g + 1) + tap];
    }
    __nv_bfloat16 h = __float2bfloat16(v);
    g_Wh[idx] = h;
    g_Wl[idx] = __float2bfloat16(v - __bfloat162float(h));
}

template<int ROWS, int LVALID>
__global__ __launch_bounds__(256) void prep_x(const float* __restrict__ X,
                                              __nv_bfloat16* __restrict__ Xh,
                                              __nv_bfloat16* __restrict__ Xl)
{
    int idx = blockIdx.x * 256 + threadIdx.x;
    const int T = NB * ROWS * (KP / 4);
    if (idx >= T) return;
    int e4  = idx % (KP / 4);
    int row = idx / (KP / 4);
    int b = row / ROWS;
    int p = row - b * ROWS;
    int e0 = e4 * 4;
    float4 v = make_float4(0.f, 0.f, 0.f, 0.f);
    if (p < LVALID && e0 < NE)
        v = *(const float4*)&X[((size_t)(b * LVALID + p)) * NE + e0];
    __nv_bfloat16 h[4], l[4];
    float vv[4] = {v.x, v.y, v.z, v.w};
#pragma unroll
    for (int j = 0; j < 4; j++) {
        h[j] = __float2bfloat16(vv[j]);
        l[j] = __float2bfloat16(vv[j] - __bfloat162float(h[j]));
    }
    size_t o = (size_t)row * KP + e0;
    *(__nv_bfloat162*)&Xh[o]     = *(__nv_bfloat162*)&h[0];
    *(__nv_bfloat162*)&Xh[o + 2] = *(__nv_bfloat162*)&h[2];
    *(__nv_bfloat162*)&Xl[o]     = *(__nv_bfloat162*)&l[0];
    *(__nv_bfloat162*)&Xl[o + 2] = *(__nv_bfloat162*)&l[2];
}

// ---------------- merged conv GEMM: proven compute + cp.async, distance-2 prefetch ----------------
// 1D grid 864, longest-first: [0,288)=g2, [288,576)=g1, [576,864)=g0.
// Within section: sub<256 -> doc (m0=(sub&1)*128, b=sub>>1); else query (b0=(sub-256)*4).
#define S_AH 0
#define S_AL 18432
#define S_BH 36864
#define S_BL 55296
#define C_STG 73728
#define C_SQ  (3 * C_STG)
#define C_TOT (C_SQ + 512)

__global__ __launch_bounds__(256) void convmma(const float* __restrict__ bs0,
                                               const float* __restrict__ bs1,
                                               const float* __restrict__ bs2)
{
    constexpr int NFRAG = 8, NJ2 = 4, SA = 72;

    extern __shared__ char sm[];
    const uint32_t sbase = smem_u32(sm);

    const int tid  = threadIdx.x;
    const int wid  = tid >> 5;
    const int lane = tid & 31;
    const int wr  = wid >> 1;
    const int wcn = wid & 1;
    const int mr = wr * 32;
    const int nc = wcn * 64;

    // block decode (longest work first)
    const int bidx = blockIdx.x;
    const int g   = (bidx < 288) ? 2 : ((bidx < 576) ? 1 : 0);
    const int sub = bidx - ((g == 2) ? 0 : ((g == 1) ? 288 : 576));
    const bool isq = (sub >= 256);
    const int m0 = isq ? 0 : ((sub & 1) * 128);
    const int b0 = isq ? (sub - 256) * 4 : (sub >> 1);

    const int wbase = (g == 0) ? 0 : ((g == 1) ? 40960 : 122880);
    const int wrs = (g + 1) * KP;
    const float* bias = (g == 0) ? bs0 : ((g == 1) ? bs1 : bs2);
    const __nv_bfloat16* Xh = isq ? g_Xqh : g_Xdh;
    const __nv_bfloat16* Xl = isq ? g_Xql : g_Xdl;
    const int XR = isq ? XQROWS : XDROWS;

    if (tid < 128) *(float*)(sm + C_SQ + tid * 4) = 0.f;

    const int lg = lane >> 3, l7 = lane & 7;
    const uint32_t a_off = ((mr + (lg & 1) * 8 + l7) * SA + ((lg >> 1) * 8)) * 2;
    const uint32_t b_off = ((nc + (lg >> 1) * 8 + l7) * SA + ((lg & 1) * 8)) * 2;

    float acc[2][NFRAG][4];
#pragma unroll
    for (int f = 0; f < 2; f++)
#pragma unroll
        for (int j = 0; j < NFRAG; j++)
#pragma unroll
            for (int t = 0; t < 4; t++) acc[f][j][t] = 0.f;

    const int NCC = 5 * (g + 1);

    auto load_stage = [&](int s) {
        uint32_t sb = sbase + (uint32_t)(s % 3) * C_STG;
        int tap = s / 5;
        int e0 = (s - tap * 5) * 64;
        const __nv_bfloat16* bh = g_Wh + wbase + tap * KP + e0;
        const __nv_bfloat16* bl = g_Wl + wbase + tap * KP + e0;
#pragma unroll
        for (int it = 0; it < 4; it++) {
            int u = tid + it * 256;
            int r = u >> 3, c = u & 7;
            size_t arow = isq ? ((size_t)(b0 + (r >> 5)) * XR + (r & 31) + tap)
                              : ((size_t)b0 * XR + m0 + r + tap);
            size_t go = arow * KP + e0 + c * 8;
            uint32_t dof = r * 144 + c * 16;
            cpa16(sb + S_AH + dof, Xh + go);
            cpa16(sb + S_AL + dof, Xl + go);
            cpa16(sb + S_BH + dof, bh + (size_t)r * wrs + c * 8);
            cpa16(sb + S_BL + dof, bl + (size_t)r * wrs + c * 8);
        }
    };

    // distance-2 prefetch on 3-stage ring
    load_stage(0);
    CP_COMMIT();
    load_stage(1);
    CP_COMMIT();

    for (int cc = 0; cc < NCC; cc++) {
        CP_WAIT(1);                 // chunk cc has landed (cc+1 may still be in flight)
        __syncthreads();
        if (cc + 2 < NCC) { load_stage(cc + 2); CP_COMMIT(); }  // stage (cc+2)%3 == (cc-1)%3: done & synced

        const uint32_t sb = sbase + (uint32_t)(cc % 3) * C_STG;
#pragma unroll
        for (int ks = 0; ks < 4; ks++) {
            uint32_t ahf[2][4], alf[2][4];
            ldsm4(ahf[0], sb + S_AH + a_off + ks * 32);
            ldsm4(ahf[1], sb + S_AH + a_off + 16 * SA * 2 + ks * 32);
            ldsm4(alf[0], sb + S_AL + a_off + ks * 32);
            ldsm4(alf[1], sb + S_AL + a_off + 16 * SA * 2 + ks * 32);
            uint32_t bhf[NJ2][4], blf[NJ2][4];
#pragma unroll
            for (int j2 = 0; j2 < NJ2; j2++) {
                ldsm4(bhf[j2], sb + S_BH + b_off + j2 * 16 * SA * 2 + ks * 32);
                ldsm4(blf[j2], sb + S_BL + b_off + j2 * 16 * SA * 2 + ks * 32);
            }
#pragma unroll
            for (int f = 0; f < 2; f++)
#pragma unroll
                for (int j = 0; j < NFRAG; j++) {
                    const uint32_t* bhp = &bhf[j >> 1][(j & 1) * 2];
                    const uint32_t* blp = &blf[j >> 1][(j & 1) * 2];
                    mma16816(acc[f][j], ahf[f], bhp);
                    mma16816(acc[f][j], ahf[f], blp);
                    mma16816(acc[f][j], alf[f], bhp);
                }
        }
    }

    // epilogue: bias + relu + rowwise L2 norm (proven), direct bf16 hi/lo store
    const int lq = lane >> 2, lr = lane & 3;
    float ssq_p[2][2] = {{0.f, 0.f}, {0.f, 0.f}};
#pragma unroll
    for (int f = 0; f < 2; f++)
#pragma unroll
        for (int j = 0; j < NFRAG; j++) {
            float bv0 = __ldg(&bias[nc + j * 8 + 2 * lr]);
            float bv1 = __ldg(&bias[nc + j * 8 + 2 * lr + 1]);
            float v0 = fmaxf(acc[f][j][0] + bv0, 0.f);
            float v1 = fmaxf(acc[f][j][1] + bv1, 0.f);
            float v2 = fmaxf(acc[f][j][2] + bv0, 0.f);
            float v3 = fmaxf(acc[f][j][3] + bv1, 0.f);
            acc[f][j][0] = v0; acc[f][j][1] = v1; acc[f][j][2] = v2; acc[f][j][3] = v3;
            ssq_p[f][0] += v0 * v0 + v1 * v1;
            ssq_p[f][1] += v2 * v2 + v3 * v3;
        }
    __syncthreads();
#pragma unroll
    for (int f = 0; f < 2; f++)
#pragma unroll
        for (int h = 0; h < 2; h++) {
            float v = ssq_p[f][h];
            v += __shfl_xor_sync(0xffffffffu, v, 1);
            v += __shfl_xor_sync(0xffffffffu, v, 2);
            if (lr == 0)
                atomicAdd((float*)(sm + C_SQ + (mr + f * 16 + h * 8 + lq) * 4), v);
        }
    __syncthreads();

    __nv_bfloat16* OH = isq ? g_Qh2 : g_Dh2;
    __nv_bfloat16* OL = isq ? g_Ql2 : g_Dl2;
#pragma unroll
    for (int f = 0; f < 2; f++)
#pragma unroll
        for (int h = 0; h < 2; h++) {
            int r = mr + f * 16 + h * 8 + lq;
            float inv = 1.f / (sqrtf(*(float*)(sm + C_SQ + r * 4)) + 1e-13f);
            bool valid;
            size_t orow;
            if (isq) {
                int pos = r & 31;
                valid = pos < NQ;
                orow = (size_t)(b0 + (r >> 5)) * 32 + pos;
            } else {
                valid = true;
                orow = (size_t)b0 * ND + m0 + r;
            }
            if (!valid) continue;
            size_t ob = orow * 384 + g * 128;
#pragma unroll
            for (int j = 0; j < NFRAG; j++) {
                float v0 = acc[f][j][h * 2 + 0] * inv;
                float v1 = acc[f][j][h * 2 + 1] * inv;
                __nv_bfloat16 h0 = __float2bfloat16(v0);
                __nv_bfloat16 h1 = __float2bfloat16(v1);
                __nv_bfloat16 l0 = __float2bfloat16(v0 - __bfloat162float(h0));
                __nv_bfloat16 l1 = __float2bfloat16(v1 - __bfloat162float(h1));
                __nv_bfloat162 ph; ph.x = h0; ph.y = h1;
                __nv_bfloat162 pl; pl.x = l0; pl.y = l1;
                size_t o = ob + nc + j * 8 + 2 * lr;
                *(__nv_bfloat162*)&OH[o] = ph;
                *(__nv_bfloat162*)&OL[o] = pl;
            }
        }
}

__global__ __launch_bounds__(256) void zero_pk()
{
    int i = blockIdx.x * 256 + threadIdx.x;
    if (i < NB * 9 * 30 * 11) g_pk[i] = 0.f;
}

// ---------------- pool: proven round-7 kernel (unchanged) ----------------
#define PM_AH 0
#define PM_AL 4608
#define PM_BH 9216
#define PM_BL 27648
#define PM_TOT 46080

__global__ __launch_bounds__(256) void poolmma(const float* __restrict__ qmask,
                                               const float* __restrict__ dmask)
{
    extern __shared__ char sm[];
    const uint32_t sbase = smem_u32(sm);

    const int tid  = threadIdx.x;
    const int wid  = tid >> 5;
    const int lane = tid & 31;
    const int nc = wid * 16;

    const int b    = blockIdx.x;
    const int pair = blockIdx.y;
    const int z    = blockIdx.z;
    const int gi = pair / 3;
    const int gt = pair - gi * 3;

    const int lg = lane >> 3, l7 = lane & 7;
    const uint32_t a_off = (((lg & 1) * 8 + l7) * 72 + ((lg >> 1) * 8)) * 2;
    const uint32_t b_off = ((nc + (lg >> 1) * 8 + l7) * 72 + ((lg & 1) * 8)) * 2;

    float acc[2][2][4];
#pragma unroll
    for (int f = 0; f < 2; f++)
#pragma unroll
        for (int j = 0; j < 2; j++)
#pragma unroll
            for (int t = 0; t < 4; t++) acc[f][j][t] = 0.f;

    for (int cc = 0; cc < 2; cc++) {
        const int e0 = cc * 64;
        const __nv_bfloat16* ah = g_Qh2 + ((size_t)b * 32) * 384 + gi * 128 + e0;
        const __nv_bfloat16* al = g_Ql2 + ((size_t)b * 32) * 384 + gi * 128 + e0;
        const __nv_bfloat16* bh = g_Dh2 + ((size_t)(b * ND + z * 128)) * 384 + gt * 128 + e0;
        const __nv_bfloat16* bl = g_Dl2 + ((size_t)(b * ND + z * 128)) * 384 + gt * 128 + e0;

        __syncthreads();
        {
            int r = tid >> 3, c = tid & 7;
            *(uint4*)(sm + PM_AH + r * 144 + c * 16) = *(const uint4*)(ah + (size_t)r * 384 + c * 8);
            *(uint4*)(sm + PM_AL + r * 144 + c * 16) = *(const uint4*)(al + (size_t)r * 384 + c * 8);
        }
#pragma unroll
        for (int u = tid; u < 1024; u += 256) {
            int r = u >> 3, c = u & 7;
            *(uint4*)(sm + PM_BH + r * 144 + c * 16) = *(const uint4*)(bh + (size_t)r * 384 + c * 8);
            *(uint4*)(sm + PM_BL + r * 144 + c * 16) = *(const uint4*)(bl + (size_t)r * 384 + c * 8);
        }
        __syncthreads();

#pragma unroll
        for (int ks = 0; ks < 4; ks++) {
            uint32_t ahf[2][4], alf[2][4], bhf[4], blf[4];
            ldsm4(ahf[0], sbase + PM_AH + a_off + ks * 32);
            ldsm4(ahf[1], sbase + PM_AH + a_off + 16 * 144 + ks * 32);
            ldsm4(alf[0], sbase + PM_AL + a_off + ks * 32);
            ldsm4(alf[1], sbase + PM_AL + a_off + 16 * 144 + ks * 32);
            ldsm4(bhf, sbase + PM_BH + b_off + ks * 32);
            ldsm4(blf, sbase + PM_BL + b_off + ks * 32);
#pragma unroll
            for (int f = 0; f < 2; f++)
#pragma unroll
                for (int j = 0; j < 2; j++) {
                    mma16816(acc[f][j], ahf[f], &bhf[j * 2]);
                    mma16816(acc[f][j], ahf[f], &blf[j * 2]);
                    mma16816(acc[f][j], alf[f], &bhf[j * 2]);
                }
        }
    }

    const int lq = lane >> 2, lr = lane & 3;
    const float U1 = 0.13533528323661270f;   // e^-2
    const float U2 = 0.018315638888734179f;  // e^-4

    float qacc[4][11];
#pragma unroll
    for (int s = 0; s < 4; s++)
#pragma unroll
        for (int k = 0; k < 11; k++) qacc[s][k] = 0.f;

#pragma unroll
    for (int f = 0; f < 2; f++)
#pragma unroll
        for (int h = 0; h < 2; h++) {
            int row = f * 16 + h * 8 + lq;
            float qmv = (row < NQ) ? __ldg(&qmask[b * NQ + row]) : 0.f;
            int slot = f * 2 + h;
#pragma unroll
            for (int j = 0; j < 2; j++)
#pragma unroll
                for (int e = 0; e < 2; e++) {
                    int col = z * 128 + nc + j * 8 + 2 * lr + e;
                    float m = qmv * __ldg(&dmask[b * ND + col]);
                    float c = acc[f][j][h * 2 + e] * m;
                    float x = c - 0.9f;
                    float e1 = __expf(-50.f * x * x) * m;
                    float t  = __expf(-20.f * x);
                    float t0 = c - 1.0f;
                    qacc[slot][0] += __expf(-500000.f * t0 * t0) * m;
                    float v = e1;
                    qacc[slot][1] += v;
                    float r = t * U1;
#pragma unroll
                    for (int kk = 2; kk < 11; kk++) {
                        v *= r;
                        qacc[slot][kk] += v;
                        r *= U2;
                    }
                }
        }

#pragma unroll
    for (int s = 0; s < 4; s++)
#pragma unroll
        for (int k = 0; k < 11; k++) {
            float v = qacc[s][k];
            v += __shfl_xor_sync(0xffffffffu, v, 1);
            v += __shfl_xor_sync(0xffffffffu, v, 2);
            qacc[s][k] = v;
        }
    if (lr == 0) {
#pragma unroll
        for (int s = 0; s < 4; s++) {
            int row = (s >> 1) * 16 + (s & 1) * 8 + lq;
            if (row < NQ) {
                float* dst = &g_pk[(((size_t)(b * 9 + pair)) * 30 + row) * 11];
#pragma unroll
                for (int k = 0; k < 11; k++) atomicAdd(&dst[k], qacc[s][k]);
            }
        }
    }
}

// ---------------- finish ----------------
__global__ __launch_bounds__(352) void finish_kernel(const float* __restrict__ qmask)
{
    __shared__ float t[330];
    const int b = blockIdx.x, pair = blockIdx.y, tid = threadIdx.x;
    if (tid < 330) {
        int row = tid / 11;
        float pk = fmaxf(g_pk[(((size_t)(b * 9 + pair)) * 30 + row) * 11 + tid % 11], 1e-10f);
        t[tid] = __logf(pk) * 0.01f * __ldg(&qmask[b * NQ + row]);
    }
    __syncthreads();
    if (tid < 11) {
        float s = 0.f;
#pragma unroll
        for (int q = 0; q < NQ; q++) s += t[q * 11 + tid];
        g_feat[b * 99 + pair * 11 + tid] = s;
    }
}

__global__ void final_kernel(const float* __restrict__ dw, float* __restrict__ out)
{
    int b = threadIdx.x;
    if (b < NB) {
        float s = 0.f;
#pragma unroll
        for (int j = 0; j < 99; j++) s += g_feat[b * 99 + j] * dw[j];
        out[b] = s;
    }
}

// ---------------- launch ----------------
extern "C" void kernel_launch(void* const* d_in, const int* in_sizes, int n_in,
                              void* d_out, int out_size)
{
    const float* qe    = (const float*)d_in[0];
    const float* de    = (const float*)d_in[1];
    const float* qmask = (const float*)d_in[2];
    const float* dmask = (const float*)d_in[3];
    const float* w1    = (const float*)d_in[4];
    const float* b1    = (const float*)d_in[5];
    const float* w2    = (const float*)d_in[6];
    const float* b2    = (const float*)d_in[7];
    const float* w3    = (const float*)d_in[8];
    const float* b3    = (const float*)d_in[9];
    const float* dw    = (const float*)d_in[10];
    float* out = (float*)d_out;

    __nv_bfloat16 *xqh, *xql, *xdh, *xdl;
    cudaGetSymbolAddress((void**)&xqh, g_Xqh);
    cudaGetSymbolAddress((void**)&xql, g_Xql);
    cudaGetSymbolAddress((void**)&xdh, g_Xdh);
    cudaGetSymbolAddress((void**)&xdl, g_Xdl);

    prep_w<<<(245760 + 255) / 256, 256>>>(w1, w2, w3);
    prep_x<XQROWS, NQ><<<(NB * XQROWS * (KP / 4) + 255) / 256, 256>>>(qe, xqh, xql);
    prep_x<XDROWS, ND><<<(NB * XDROWS * (KP / 4) + 255) / 256, 256>>>(de, xdh, xdl);

    cudaFuncSetAttribute(convmma, cudaFuncAttributeMaxDynamicSharedMemorySize, C_TOT);
    convmma<<<864, 256, C_TOT>>>(b1, b2, b3);

    zero_pk<<<(NB * 9 * 30 * 11 + 255) / 256, 256>>>();

    cudaFuncSetAttribute(poolmma, cudaFuncAttributeMaxDynamicSharedMemorySize, PM_TOT);
    poolmma<<<dim3(NB, 9, 2), 256, PM_TOT>>>(qmask, dmask);

    finish_kernel<<<dim3(NB, 9), 352>>>(qmask);
    final_kernel<<<1, 128>>>(dw, out);
}

// round 11
// speedup vs baseline: 5.1380x; 1.0092x over previous
#include <cuda_runtime.h>
#include <cuda_bf16.h>
#include <math.h>
#include <cstdint>

#define NB 128
#define NQ 30
#define ND 256
#define NE 300
#define KP 320
#define XQROWS 34
#define XDROWS 258

// ---------------- scratch ----------------
__device__ __align__(16) __nv_bfloat16 g_Xqh[NB * XQROWS * KP];
__device__ __align__(16) __nv_bfloat16 g_Xql[NB * XQROWS * KP];
__device__ __align__(16) __nv_bfloat16 g_Xdh[NB * XDROWS * KP];
__device__ __align__(16) __nv_bfloat16 g_Xdl[NB * XDROWS * KP];
__device__ __align__(16) __nv_bfloat16 g_Wh[245760];
__device__ __align__(16) __nv_bfloat16 g_Wl[245760];
__device__ __align__(16) __nv_bfloat16 g_Qh2[NB * 32 * 384];   // rows 30,31 stay zero
__device__ __align__(16) __nv_bfloat16 g_Ql2[NB * 32 * 384];
__device__ __align__(16) __nv_bfloat16 g_Dh2[NB * ND * 384];
__device__ __align__(16) __nv_bfloat16 g_Dl2[NB * ND * 384];
__device__ float g_pk[NB * 9 * 30 * 11];
__device__ float g_feat[NB * 99];

__device__ __forceinline__ uint32_t smem_u32(const void* p) {
    uint32_t a;
    asm("{ .reg .u64 t; cvta.to.shared.u64 t, %1; cvt.u32.u64 %0, t; }" : "=r"(a) : "l"(p));
    return a;
}
__device__ __forceinline__ void ldsm4(uint32_t* r, uint32_t addr) {
    asm volatile("ldmatrix.sync.aligned.m8n8.x4.shared.b16 {%0,%1,%2,%3}, [%4];"
                 : "=r"(r[0]), "=r"(r[1]), "=r"(r[2]), "=r"(r[3]) : "r"(addr));
}
__device__ __forceinline__ void mma16816(float* c, const uint32_t* a, const uint32_t* b) {
    asm volatile("mma.sync.aligned.m16n8k16.row.col.f32.bf16.bf16.f32 "
                 "{%0,%1,%2,%3}, {%4,%5,%6,%7}, {%8,%9}, {%0,%1,%2,%3};"
                 : "+f"(c[0]), "+f"(c[1]), "+f"(c[2]), "+f"(c[3])
                 : "r"(a[0]), "r"(a[1]), "r"(a[2]), "r"(a[3]), "r"(b[0]), "r"(b[1]));
}
__device__ __forceinline__ void cpa16(uint32_t dst, const void* src) {
    asm volatile("cp.async.ca.shared.global [%0], [%1], 16;" :: "r"(dst), "l"(src) : "memory");
}
#define CP_COMMIT() asm volatile("cp.async.commit_group;" ::: "memory")
#define CP_WAIT(n)  asm volatile("cp.async.wait_group %0;" :: "n"(n) : "memory")

// ---------------- prep kernels (proven) ----------------
__global__ __launch_bounds__(256) void prep_w(const float* __restrict__ w1,
                                              const float* __restrict__ w2,
                                              const float* __restrict__ w3)
{
    int idx = blockIdx.x * 256 + threadIdx.x;
    if (idx >= 245760) return;
    int g, base, rs;
    if (idx < 40960)       { g = 0; base = 0;      rs = 320; }
    else if (idx < 122880) { g = 1; base = 40960;  rs = 640; }
    else                   { g = 2; base = 122880; rs = 960; }
    int off = idx - base;
    int n = off / rs;
    int r = off - n * rs;
    int tap = r / KP;
    int e = r - tap * KP;
    float v = 0.f;
    if (e < NE) {
        const float* w = (g == 0) ? w1 : ((g == 1) ? w2 : w3);
        v = w[(n * NE + e) * (g + 1) + tap];
    }
    __nv_bfloat16 h = __float2bfloat16(v);
    g_Wh[idx] = h;
    g_Wl[idx] = __float2bfloat16(v - __bfloat162float(h));
}

template<int ROWS, int LVALID>
__global__ __launch_bounds__(256) void prep_x(const float* __restrict__ X,
                                              __nv_bfloat16* __restrict__ Xh,
                                              __nv_bfloat16* __restrict__ Xl)
{
    int idx = blockIdx.x * 256 + threadIdx.x;
    const int T = NB * ROWS * (KP / 4);
    if (idx >= T) return;
    int e4  = idx % (KP / 4);
    int row = idx / (KP / 4);
    int b = row / ROWS;
    int p = row - b * ROWS;
    int e0 = e4 * 4;
    float4 v = make_float4(0.f, 0.f, 0.f, 0.f);
    if (p < LVALID && e0 < NE)
        v = *(const float4*)&X[((size_t)(b * LVALID + p)) * NE + e0];
    __nv_bfloat16 h[4], l[4];
    float vv[4] = {v.x, v.y, v.z, v.w};
#pragma unroll
    for (int j = 0; j < 4; j++) {
        h[j] = __float2bfloat16(vv[j]);
        l[j] = __float2bfloat16(vv[j] - __bfloat162float(h[j]));
    }
    size_t o = (size_t)row * KP + e0;
    *(__nv_bfloat162*)&Xh[o]     = *(__nv_bfloat162*)&h[0];
    *(__nv_bfloat162*)&Xh[o + 2] = *(__nv_bfloat162*)&h[2];
    *(__nv_bfloat162*)&Xl[o]     = *(__nv_bfloat162*)&l[0];
    *(__nv_bfloat162*)&Xl[o + 2] = *(__nv_bfloat162*)&l[2];
}

// ---------------- merged conv GEMM: TM=64/WC=4, 2 CTAs/SM, cp.async 2-stage ----------------
// 1D grid 1728, longest-first: [0,576)=g2, [576,1152)=g1, [1152,1728)=g0.
// Within section: sub<512 -> doc (m0=(sub&3)*64, b=sub>>2); else query (b0=(sub-512)*2).
#define S_AH 0
#define S_AL 9216
#define S_BH 18432
#define S_BL 36864
#define C_STG 55296
#define C_SQ  (2 * C_STG)
#define C_TOT (C_SQ + 256)

__global__ __launch_bounds__(256, 2) void convmma(const float* __restrict__ bs0,
                                                  const float* __restrict__ bs1,
                                                  const float* __restrict__ bs2)
{
    constexpr int TM = 64, NFRAG = 4, NJ2 = 2, SA = 72;

    extern __shared__ char sm[];
    const uint32_t sbase = smem_u32(sm);

    const int tid  = threadIdx.x;
    const int wid  = tid >> 5;
    const int lane = tid & 31;
    const int wr  = wid >> 2;          // 2 m-groups of 32
    const int wcn = wid & 3;           // 4 n-groups of 32
    const int mr = wr * 32;
    const int nc = wcn * 32;

    // block decode (longest work first)
    const int bidx = blockIdx.x;
    const int g   = (bidx < 576) ? 2 : ((bidx < 1152) ? 1 : 0);
    const int sub = bidx - ((g == 2) ? 0 : ((g == 1) ? 576 : 1152));
    const bool isq = (sub >= 512);
    const int m0 = isq ? 0 : ((sub & 3) * 64);
    const int b0 = isq ? (sub - 512) * 2 : (sub >> 2);

    const int wbase = (g == 0) ? 0 : ((g == 1) ? 40960 : 122880);
    const int wrs = (g + 1) * KP;
    const float* bias = (g == 0) ? bs0 : ((g == 1) ? bs1 : bs2);
    const __nv_bfloat16* Xh = isq ? g_Xqh : g_Xdh;
    const __nv_bfloat16* Xl = isq ? g_Xql : g_Xdl;
    const int XR = isq ? XQROWS : XDROWS;

    if (tid < TM) *(float*)(sm + C_SQ + tid * 4) = 0.f;

    const int lg = lane >> 3, l7 = lane & 7;
    const uint32_t a_off = ((mr + (lg & 1) * 8 + l7) * SA + ((lg >> 1) * 8)) * 2;
    const uint32_t b_off = ((nc + (lg >> 1) * 8 + l7) * SA + ((lg & 1) * 8)) * 2;

    float acc[2][NFRAG][4];
#pragma unroll
    for (int f = 0; f < 2; f++)
#pragma unroll
        for (int j = 0; j < NFRAG; j++)
#pragma unroll
            for (int t = 0; t < 4; t++) acc[f][j][t] = 0.f;

    const int NCC = 5 * (g + 1);

    auto load_stage = [&](int s) {
        uint32_t sb = sbase + (uint32_t)(s & 1) * C_STG;
        int tap = s / 5;
        int e0 = (s - tap * 5) * 64;
        const __nv_bfloat16* bh = g_Wh + wbase + tap * KP + e0;
        const __nv_bfloat16* bl = g_Wl + wbase + tap * KP + e0;
        // A: 64 rows x 8 units = 512 -> 2 iters
#pragma unroll
        for (int it = 0; it < 2; it++) {
            int u = tid + it * 256;
            int r = u >> 3, c = u & 7;
            size_t arow = isq ? ((size_t)(b0 + (r >> 5)) * XR + (r & 31) + tap)
                              : ((size_t)b0 * XR + m0 + r + tap);
            size_t go = arow * KP + e0 + c * 8;
            uint32_t dof = r * 144 + c * 16;
            cpa16(sb + S_AH + dof, Xh + go);
            cpa16(sb + S_AL + dof, Xl + go);
        }
        // B: 128 rows x 8 units = 1024 -> 4 iters
#pragma unroll
        for (int it = 0; it < 4; it++) {
            int u = tid + it * 256;
            int r = u >> 3, c = u & 7;
            uint32_t dof = r * 144 + c * 16;
            cpa16(sb + S_BH + dof, bh + (size_t)r * wrs + c * 8);
            cpa16(sb + S_BL + dof, bl + (size_t)r * wrs + c * 8);
        }
    };

    load_stage(0);
    CP_COMMIT();

    for (int cc = 0; cc < NCC; cc++) {
        if (cc + 1 < NCC) { load_stage(cc + 1); CP_COMMIT(); }  // other stage: freed by end-of-prev-iter barrier
        if (cc + 1 < NCC) CP_WAIT(1); else CP_WAIT(0);
        __syncthreads();

        const uint32_t sb = sbase + (uint32_t)(cc & 1) * C_STG;
#pragma unroll
        for (int ks = 0; ks < 4; ks++) {
            uint32_t ahf[2][4], alf[2][4];
            ldsm4(ahf[0], sb + S_AH + a_off + ks * 32);
            ldsm4(ahf[1], sb + S_AH + a_off + 16 * SA * 2 + ks * 32);
            ldsm4(alf[0], sb + S_AL + a_off + ks * 32);
            ldsm4(alf[1], sb + S_AL + a_off + 16 * SA * 2 + ks * 32);
            uint32_t bhf[NJ2][4], blf[NJ2][4];
#pragma unroll
            for (int j2 = 0; j2 < NJ2; j2++) {
                ldsm4(bhf[j2], sb + S_BH + b_off + j2 * 16 * SA * 2 + ks * 32);
                ldsm4(blf[j2], sb + S_BL + b_off + j2 * 16 * SA * 2 + ks * 32);
            }
#pragma unroll
            for (int f = 0; f < 2; f++)
#pragma unroll
                for (int j = 0; j < NFRAG; j++) {
                    const uint32_t* bhp = &bhf[j >> 1][(j & 1) * 2];
                    const uint32_t* blp = &blf[j >> 1][(j & 1) * 2];
                    mma16816(acc[f][j], ahf[f], bhp);
                    mma16816(acc[f][j], ahf[f], blp);
                    mma16816(acc[f][j], alf[f], bhp);
                }
        }
        __syncthreads();     // stage consumed; safe for next iter's load to overwrite the other stage
    }

    // epilogue: bias + relu + rowwise L2 norm (proven), direct bf16 hi/lo store
    const int lq = lane >> 2, lr = lane & 3;
    float ssq_p[2][2] = {{0.f, 0.f}, {0.f, 0.f}};
#pragma unroll
    for (int f = 0; f < 2; f++)
#pragma unroll
        for (int j = 0; j < NFRAG; j++) {
            float bv0 = __ldg(&bias[nc + j * 8 + 2 * lr]);
            float bv1 = __ldg(&bias[nc + j * 8 + 2 * lr + 1]);
            float v0 = fmaxf(acc[f][j][0] + bv0, 0.f);
            float v1 = fmaxf(acc[f][j][1] + bv1, 0.f);
            float v2 = fmaxf(acc[f][j][2] + bv0, 0.f);
            float v3 = fmaxf(acc[f][j][3] + bv1, 0.f);
            acc[f][j][0] = v0; acc[f][j][1] = v1; acc[f][j][2] = v2; acc[f][j][3] = v3;
            ssq_p[f][0] += v0 * v0 + v1 * v1;
            ssq_p[f][1] += v2 * v2 + v3 * v3;
        }
#pragma unroll
    for (int f = 0; f < 2; f++)
#pragma unroll
        for (int h = 0; h < 2; h++) {
            float v = ssq_p[f][h];
            v += __shfl_xor_sync(0xffffffffu, v, 1);
            v += __shfl_xor_sync(0xffffffffu, v, 2);
            if (lr == 0)
                atomicAdd((float*)(sm + C_SQ + (mr + f * 16 + h * 8 + lq) * 4), v);
        }
    __syncthreads();

    __nv_bfloat16* OH = isq ? g_Qh2 : g_Dh2;
    __nv_bfloat16* OL = isq ? g_Ql2 : g_Dl2;
#pragma unroll
    for (int f = 0; f < 2; f++)
#pragma unroll
        for (int h = 0; h < 2; h++) {
            int r = mr + f * 16 + h * 8 + lq;            // 0..63
            float inv = 1.f / (sqrtf(*(float*)(sm + C_SQ + r * 4)) + 1e-13f);
            bool valid;
            size_t orow;
            if (isq) {
                int pos = r & 31;
                valid = pos < NQ;
                orow = (size_t)(b0 + (r >> 5)) * 32 + pos;
            } else {
                valid = true;
                orow = (size_t)b0 * ND + m0 + r;
            }
            if (!valid) continue;
            size_t ob = orow * 384 + g * 128;
#pragma unroll
            for (int j = 0; j < NFRAG; j++) {
                float v0 = acc[f][j][h * 2 + 0] * inv;
                float v1 = acc[f][j][h * 2 + 1] * inv;
                __nv_bfloat16 h0 = __float2bfloat16(v0);
                __nv_bfloat16 h1 = __float2bfloat16(v1);
                __nv_bfloat16 l0 = __float2bfloat16(v0 - __bfloat162float(h0));
                __nv_bfloat16 l1 = __float2bfloat16(v1 - __bfloat162float(h1));
                __nv_bfloat162 ph; ph.x = h0; ph.y = h1;
                __nv_bfloat162 pl; pl.x = l0; pl.y = l1;
                size_t o = ob + nc + j * 8 + 2 * lr;
                *(__nv_bfloat162*)&OH[o] = ph;
                *(__nv_bfloat162*)&OL[o] = pl;
            }
        }
}

__global__ __launch_bounds__(256) void zero_pk()
{
    int i = blockIdx.x * 256 + threadIdx.x;
    if (i < NB * 9 * 30 * 11) g_pk[i] = 0.f;
}

// ---------------- pool: proven round-7 kernel (unchanged) ----------------
#define PM_AH 0
#define PM_AL 4608
#define PM_BH 9216
#define PM_BL 27648
#define PM_TOT 46080

__global__ __launch_bounds__(256) void poolmma(const float* __restrict__ qmask,
                                               const float* __restrict__ dmask)
{
    extern __shared__ char sm[];
    const uint32_t sbase = smem_u32(sm);

    const int tid  = threadIdx.x;
    const int wid  = tid >> 5;
    const int lane = tid & 31;
    const int nc = wid * 16;

    const int b    = blockIdx.x;
    const int pair = blockIdx.y;
    const int z    = blockIdx.z;
    const int gi = pair / 3;
    const int gt = pair - gi * 3;

    const int lg = lane >> 3, l7 = lane & 7;
    const uint32_t a_off = (((lg & 1) * 8 + l7) * 72 + ((lg >> 1) * 8)) * 2;
    const uint32_t b_off = ((nc + (lg >> 1) * 8 + l7) * 72 + ((lg & 1) * 8)) * 2;

    float acc[2][2][4];
#pragma unroll
    for (int f = 0; f < 2; f++)
#pragma unroll
        for (int j = 0; j < 2; j++)
#pragma unroll
            for (int t = 0; t < 4; t++) acc[f][j][t] = 0.f;

    for (int cc = 0; cc < 2; cc++) {
        const int e0 = cc * 64;
        const __nv_bfloat16* ah = g_Qh2 + ((size_t)b * 32) * 384 + gi * 128 + e0;
        const __nv_bfloat16* al = g_Ql2 + ((size_t)b * 32) * 384 + gi * 128 + e0;
        const __nv_bfloat16* bh = g_Dh2 + ((size_t)(b * ND + z * 128)) * 384 + gt * 128 + e0;
        const __nv_bfloat16* bl = g_Dl2 + ((size_t)(b * ND + z * 128)) * 384 + gt * 128 + e0;

        __syncthreads();
        {
            int r = tid >> 3, c = tid & 7;
            *(uint4*)(sm + PM_AH + r * 144 + c * 16) = *(const uint4*)(ah + (size_t)r * 384 + c * 8);
            *(uint4*)(sm + PM_AL + r * 144 + c * 16) = *(const uint4*)(al + (size_t)r * 384 + c * 8);
        }
#pragma unroll
        for (int u = tid; u < 1024; u += 256) {
            int r = u >> 3, c = u & 7;
            *(uint4*)(sm + PM_BH + r * 144 + c * 16) = *(const uint4*)(bh + (size_t)r * 384 + c * 8);
            *(uint4*)(sm + PM_BL + r * 144 + c * 16) = *(const uint4*)(bl + (size_t)r * 384 + c * 8);
        }
        __syncthreads();

#pragma unroll
        for (int ks = 0; ks < 4; ks++) {
            uint32_t ahf[2][4], alf[2][4], bhf[4], blf[4];
            ldsm4(ahf[0], sbase + PM_AH + a_off + ks * 32);
            ldsm4(ahf[1], sbase + PM_AH + a_off + 16 * 144 + ks * 32);
            ldsm4(alf[0], sbase + PM_AL + a_off + ks * 32);
            ldsm4(alf[1], sbase + PM_AL + a_off + 16 * 144 + ks * 32);
            ldsm4(bhf, sbase + PM_BH + b_off + ks * 32);
            ldsm4(blf, sbase + PM_BL + b_off + ks * 32);
#pragma unroll
            for (int f = 0; f < 2; f++)
#pragma unroll
                for (int j = 0; j < 2; j++) {
                    mma16816(acc[f][j], ahf[f], &bhf[j * 2]);
                    mma16816(acc[f][j], ahf[f], &blf[j * 2]);
                    mma16816(acc[f][j], alf[f], &bhf[j * 2]);
                }
        }
    }

    const int lq = lane >> 2, lr = lane & 3;
    const float U1 = 0.13533528323661270f;   // e^-2
    const float U2 = 0.018315638888734179f;  // e^-4

    float qacc[4][11];
#pragma unroll
    for (int s = 0; s < 4; s++)
#pragma unroll
        for (int k = 0; k < 11; k++) qacc[s][k] = 0.f;

#pragma unroll
    for (int f = 0; f < 2; f++)
#pragma unroll
        for (int h = 0; h < 2; h++) {
            int row = f * 16 + h * 8 + lq;
            float qmv = (row < NQ) ? __ldg(&qmask[b * NQ + row]) : 0.f;
            int slot = f * 2 + h;
#pragma unroll
            for (int j = 0; j < 2; j++)
#pragma unroll
                for (int e = 0; e < 2; e++) {
                    int col = z * 128 + nc + j * 8 + 2 * lr + e;
                    float m = qmv * __ldg(&dmask[b * ND + col]);
                    float c = acc[f][j][h * 2 + e] * m;
                    float x = c - 0.9f;
                    float e1 = __expf(-50.f * x * x) * m;
                    float t  = __expf(-20.f * x);
                    float t0 = c - 1.0f;
                    qacc[slot][0] += __expf(-500000.f * t0 * t0) * m;
                    float v = e1;
                    qacc[slot][1] += v;
                    float r = t * U1;
#pragma unroll
                    for (int kk = 2; kk < 11; kk++) {
                        v *= r;
                        qacc[slot][kk] += v;
                        r *= U2;
                    }
                }
        }

#pragma unroll
    for (int s = 0; s < 4; s++)
#pragma unroll
        for (int k = 0; k < 11; k++) {
            float v = qacc[s][k];
            v += __shfl_xor_sync(0xffffffffu, v, 1);
            v += __shfl_xor_sync(0xffffffffu, v, 2);
            qacc[s][k] = v;
        }
    if (lr == 0) {
#pragma unroll
        for (int s = 0; s < 4; s++) {
            int row = (s >> 1) * 16 + (s & 1) * 8 + lq;
            if (row < NQ) {
                float* dst = &g_pk[(((size_t)(b * 9 + pair)) * 30 + row) * 11];
#pragma unroll
                for (int k = 0; k < 11; k++) atomicAdd(&dst[k], qacc[s][k]);
            }
        }
    }
}

// ---------------- finish ----------------
__global__ __launch_bounds__(352) void finish_kernel(const float* __restrict__ qmask)
{
    __shared__ float t[330];
    const int b = blockIdx.x, pair = blockIdx.y, tid = threadIdx.x;
    if (tid < 330) {
        int row = tid / 11;
        float pk = fmaxf(g_pk[(((size_t)(b * 9 + pair)) * 30 + row) * 11 + tid % 11], 1e-10f);
        t[tid] = __logf(pk) * 0.01f * __ldg(&qmask[b * NQ + row]);
    }
    __syncthreads();
    if (tid < 11) {
        float s = 0.f;
#pragma unroll
        for (int q = 0; q < NQ; q++) s += t[q * 11 + tid];
        g_feat[b * 99 + pair * 11 + tid] = s;
    }
}

__global__ void final_kernel(const float* __restrict__ dw, float* __restrict__ out)
{
    int b = threadIdx.x;
    if (b < NB) {
        float s = 0.f;
#pragma unroll
        for (int j = 0; j < 99; j++) s += g_feat[b * 99 + j] * dw[j];
        out[b] = s;
    }
}

// ---------------- launch ----------------
extern "C" void kernel_launch(void* const* d_in, const int* in_sizes, int n_in,
                              void* d_out, int out_size)
{
    const float* qe    = (const float*)d_in[0];
    const float* de    = (const float*)d_in[1];
    const float* qmask = (const float*)d_in[2];
    const float* dmask = (const float*)d_in[3];
    const float* w1    = (const float*)d_in[4];
    const float* b1    = (const float*)d_in[5];
    const float* w2    = (const float*)d_in[6];
    const float* b2    = (const float*)d_in[7];
    const float* w3    = (const float*)d_in[8];
    const float* b3    = (const float*)d_in[9];
    const float* dw    = (const float*)d_in[10];
    float* out = (float*)d_out;

    __nv_bfloat16 *xqh, *xql, *xdh, *xdl;
    cudaGetSymbolAddress((void**)&xqh, g_Xqh);
    cudaGetSymbolAddress((void**)&xql, g_Xql);
    cudaGetSymbolAddress((void**)&xdh, g_Xdh);
    cudaGetSymbolAddress((void**)&xdl, g_Xdl);

    prep_w<<<(245760 + 255) / 256, 256>>>(w1, w2, w3);
    prep_x<XQROWS, NQ><<<(NB * XQROWS * (KP / 4) + 255) / 256, 256>>>(qe, xqh, xql);
    prep_x<XDROWS, ND><<<(NB * XDROWS * (KP / 4) + 255) / 256, 256>>>(de, xdh, xdl);

    cudaFuncSetAttribute(convmma, cudaFuncAttributeMaxDynamicSharedMemorySize, C_TOT);
    convmma<<<1728, 256, C_TOT>>>(b1, b2, b3);

    zero_pk<<<(NB * 9 * 30 * 11 + 255) / 256, 256>>>();

    cudaFuncSetAttribute(poolmma, cudaFuncAttributeMaxDynamicSharedMemorySize, PM_TOT);
    poolmma<<<dim3(NB, 9, 2), 256, PM_TOT>>>(qmask, dmask);

    finish_kernel<<<dim3(NB, 9), 352>>>(qmask);
    final_kernel<<<1, 128>>>(dw, out);
}

// round 13
// speedup vs baseline: 5.5608x; 1.0823x over previous
#include <cuda_runtime.h>
#include <cuda_bf16.h>
#include <math.h>
#include <cstdint>

#define NB 128
#define NQ 30
#define ND 256
#define NE 300
#define KP 320
#define XQROWS 34
#define XDROWS 258

// ---------------- scratch ----------------
__device__ __align__(16) __nv_bfloat16 g_Xqh[NB * XQROWS * KP];
__device__ __align__(16) __nv_bfloat16 g_Xql[NB * XQROWS * KP];
__device__ __align__(16) __nv_bfloat16 g_Xdh[NB * XDROWS * KP];
__device__ __align__(16) __nv_bfloat16 g_Xdl[NB * XDROWS * KP];
__device__ __align__(16) __nv_bfloat16 g_Wh[245760];
__device__ __align__(16) __nv_bfloat16 g_Wl[245760];
__device__ __align__(16) __nv_bfloat16 g_Qh2[NB * 32 * 384];   // rows 30,31 stay zero
__device__ __align__(16) __nv_bfloat16 g_Ql2[NB * 32 * 384];
__device__ __align__(16) __nv_bfloat16 g_Dh2[NB * ND * 384];
__device__ __align__(16) __nv_bfloat16 g_Dl2[NB * ND * 384];
__device__ float g_pk[NB * 9 * 30 * 11];
__device__ float g_feat[NB * 99];

__device__ __forceinline__ uint32_t smem_u32(const void* p) {
    uint32_t a;
    asm("{ .reg .u64 t; cvta.to.shared.u64 t, %1; cvt.u32.u64 %0, t; }" : "=r"(a) : "l"(p));
    return a;
}
__device__ __forceinline__ void ldsm4(uint32_t* r, uint32_t addr) {
    asm volatile("ldmatrix.sync.aligned.m8n8.x4.shared.b16 {%0,%1,%2,%3}, [%4];"
                 : "=r"(r[0]), "=r"(r[1]), "=r"(r[2]), "=r"(r[3]) : "r"(addr));
}
__device__ __forceinline__ void mma16816(float* c, const uint32_t* a, const uint32_t* b) {
    asm volatile("mma.sync.aligned.m16n8k16.row.col.f32.bf16.bf16.f32 "
                 "{%0,%1,%2,%3}, {%4,%5,%6,%7}, {%8,%9}, {%0,%1,%2,%3};"
                 : "+f"(c[0]), "+f"(c[1]), "+f"(c[2]), "+f"(c[3])
                 : "r"(a[0]), "r"(a[1]), "r"(a[2]), "r"(a[3]), "r"(b[0]), "r"(b[1]));
}
__device__ __forceinline__ void cpa16(uint32_t dst, const void* src) {
    asm volatile("cp.async.ca.shared.global [%0], [%1], 16;" :: "r"(dst), "l"(src) : "memory");
}
#define CP_COMMIT() asm volatile("cp.async.commit_group;" ::: "memory")
#define CP_WAIT(n)  asm volatile("cp.async.wait_group %0;" :: "n"(n) : "memory")

// ---------------- prep kernels (proven) ----------------
__global__ __launch_bounds__(256) void prep_w(const float* __restrict__ w1,
                                              const float* __restrict__ w2,
                                              const float* __restrict__ w3)
{
    int idx = blockIdx.x * 256 + threadIdx.x;
    if (idx >= 245760) return;
    int g, base, rs;
    if (idx < 40960)       { g = 0; base = 0;      rs = 320; }
    else if (idx < 122880) { g = 1; base = 40960;  rs = 640; }
    else                   { g = 2; base = 122880; rs = 960; }
    int off = idx - base;
    int n = off / rs;
    int r = off - n * rs;
    int tap = r / KP;
    int e = r - tap * KP;
    float v = 0.f;
    if (e < NE) {
        const float* w = (g == 0) ? w1 : ((g == 1) ? w2 : w3);
        v = w[(n * NE + e) * (g + 1) + tap];
    }
    __nv_bfloat16 h = __float2bfloat16(v);
    g_Wh[idx] = h;
    g_Wl[idx] = __float2bfloat16(v - __bfloat162float(h));
}

template<int ROWS, int LVALID>
__global__ __launch_bounds__(256) void prep_x(const float* __restrict__ X,
                                              __nv_bfloat16* __restrict__ Xh,
                                              __nv_bfloat16* __restrict__ Xl)
{
    int idx = blockIdx.x * 256 + threadIdx.x;
    const int T = NB * ROWS * (KP / 4);
    if (idx >= T) return;
    int e4  = idx % (KP / 4);
    int row = idx / (KP / 4);
    int b = row / ROWS;
    int p = row - b * ROWS;
    int e0 = e4 * 4;
    float4 v = make_float4(0.f, 0.f, 0.f, 0.f);
    if (p < LVALID && e0 < NE)
        v = *(const float4*)&X[((size_t)(b * LVALID + p)) * NE + e0];
    __nv_bfloat16 h[4], l[4];
    float vv[4] = {v.x, v.y, v.z, v.w};
#pragma unroll
    for (int j = 0; j < 4; j++) {
        h[j] = __float2bfloat16(vv[j]);
        l[j] = __float2bfloat16(vv[j] - __bfloat162float(h[j]));
    }
    size_t o = (size_t)row * KP + e0;
    *(__nv_bfloat162*)&Xh[o]     = *(__nv_bfloat162*)&h[0];
    *(__nv_bfloat162*)&Xh[o + 2] = *(__nv_bfloat162*)&h[2];
    *(__nv_bfloat162*)&Xl[o]     = *(__nv_bfloat162*)&l[0];
    *(__nv_bfloat162*)&Xl[o + 2] = *(__nv_bfloat162*)&l[2];
}

// ---------------- merged conv GEMM: TM=128/WC=2, K-chunk 32 (80B rows), 2 stages, 2 CTAs/SM ----------------
// Grid 864, longest-first: [0,288)=g2, [288,576)=g1, [576,864)=g0.
// Within section: sub<256 -> doc (m0=(sub&1)*128, b=sub>>1); else query (b0=(sub-256)*4).
// Stage: 4 tiles x 128 rows x 80B = 40960 B. 2 stages + sq = 82432 B -> 2 CTAs/SM.
#define S_AH 0
#define S_AL 10240
#define S_BH 20480
#define S_BL 30720
#define C_STG 40960
#define C_SQ  (2 * C_STG)
#define C_TOT (C_SQ + 512)

__global__ __launch_bounds__(256, 2) void convmma(const float* __restrict__ bs0,
                                                  const float* __restrict__ bs1,
                                                  const float* __restrict__ bs2)
{
    constexpr int NFRAG = 8, NJ2 = 4, SA = 40;   // 80-byte rows (16B aligned, ldmatrix conflict-free)

    extern __shared__ char sm[];
    const uint32_t sbase = smem_u32(sm);

    const int tid  = threadIdx.x;
    const int wid  = tid >> 5;
    const int lane = tid & 31;
    const int wr  = wid >> 1;          // 4 m-groups of 32
    const int wcn = wid & 1;           // 2 n-groups of 64
    const int mr = wr * 32;
    const int nc = wcn * 64;

    const int bidx = blockIdx.x;
    const int g   = (bidx < 288) ? 2 : ((bidx < 576) ? 1 : 0);
    const int sub = bidx - ((g == 2) ? 0 : ((g == 1) ? 288 : 576));
    const bool isq = (sub >= 256);
    const int m0 = isq ? 0 : ((sub & 1) * 128);
    const int b0 = isq ? (sub - 256) * 4 : (sub >> 1);

    const int wbase = (g == 0) ? 0 : ((g == 1) ? 40960 : 122880);
    const int wrs = (g + 1) * KP;
    const float* bias = (g == 0) ? bs0 : ((g == 1) ? bs1 : bs2);
    const __nv_bfloat16* Xh = isq ? g_Xqh : g_Xdh;
    const __nv_bfloat16* Xl = isq ? g_Xql : g_Xdl;
    const int XR = isq ? XQROWS : XDROWS;

    if (tid < 128) *(float*)(sm + C_SQ + tid * 4) = 0.f;

    const int lg = lane >> 3, l7 = lane & 7;
    const uint32_t a_off = ((mr + (lg & 1) * 8 + l7) * SA + ((lg >> 1) * 8)) * 2;
    const uint32_t b_off = ((nc + (lg >> 1) * 8 + l7) * SA + ((lg & 1) * 8)) * 2;

    float acc[2][NFRAG][4];
#pragma unroll
    for (int f = 0; f < 2; f++)
#pragma unroll
        for (int j = 0; j < NFRAG; j++)
#pragma unroll
            for (int t = 0; t < 4; t++) acc[f][j][t] = 0.f;

    const int NCC = 10 * (g + 1);      // K chunks of 32

    auto load_stage = [&](int s) {
        uint32_t sb = sbase + (uint32_t)(s & 1) * C_STG;
        int tap = s / 10;
        int e0 = (s - tap * 10) * 32;
        const __nv_bfloat16* bh = g_Wh + wbase + tap * KP + e0;
        const __nv_bfloat16* bl = g_Wl + wbase + tap * KP + e0;
        // each tile: 128 rows x 4 16B-units = 512 -> 2 iterations of 256 threads
#pragma unroll
        for (int it = 0; it < 2; it++) {
            int u = tid + it * 256;
            int r = u >> 2, c = u & 3;
            size_t arow = isq ? ((size_t)(b0 + (r >> 5)) * XR + (r & 31) + tap)
                              : ((size_t)b0 * XR + m0 + r + tap);
            size_t go = arow * KP + e0 + c * 8;
            uint32_t dof = r * 80 + c * 16;
            cpa16(sb + S_AH + dof, Xh + go);
            cpa16(sb + S_AL + dof, Xl + go);
            cpa16(sb + S_BH + dof, bh + (size_t)r * wrs + c * 8);
            cpa16(sb + S_BL + dof, bl + (size_t)r * wrs + c * 8);
        }
    };

    load_stage(0);
    CP_COMMIT();

    for (int cc = 0; cc < NCC; cc++) {
        if (cc + 1 < NCC) { load_stage(cc + 1); CP_COMMIT(); }  // other stage: freed by end-of-prev-iter barrier
        if (cc + 1 < NCC) CP_WAIT(1); else CP_WAIT(0);
        __syncthreads();

        const uint32_t sb = sbase + (uint32_t)(cc & 1) * C_STG;
#pragma unroll
        for (int ks = 0; ks < 2; ks++) {
            uint32_t ahf[2][4], alf[2][4];
            ldsm4(ahf[0], sb + S_AH + a_off + ks * 32);
            ldsm4(ahf[1], sb + S_AH + a_off + 16 * SA * 2 + ks * 32);
            ldsm4(alf[0], sb + S_AL + a_off + ks * 32);
            ldsm4(alf[1], sb + S_AL + a_off + 16 * SA * 2 + ks * 32);
            // B-hi pass: hi*hi + lo*hi  (register reuse keeps regs <= 128)
            {
                uint32_t bf[NJ2][4];
#pragma unroll
                for (int j2 = 0; j2 < NJ2; j2++)
                    ldsm4(bf[j2], sb + S_BH + b_off + j2 * 16 * SA * 2 + ks * 32);
#pragma unroll
                for (int f = 0; f < 2; f++)
#pragma unroll
                    for (int j = 0; j < NFRAG; j++) {
                        const uint32_t* bp = &bf[j >> 1][(j & 1) * 2];
                        mma16816(acc[f][j], ahf[f], bp);
                        mma16816(acc[f][j], alf[f], bp);
                    }
            }
            // B-lo pass: hi*lo
            {
                uint32_t bf[NJ2][4];
#pragma unroll
                for (int j2 = 0; j2 < NJ2; j2++)
                    ldsm4(bf[j2], sb + S_BL + b_off + j2 * 16 * SA * 2 + ks * 32);
#pragma unroll
                for (int f = 0; f < 2; f++)
#pragma unroll
                    for (int j = 0; j < NFRAG; j++) {
                        const uint32_t* bp = &bf[j >> 1][(j & 1) * 2];
                        mma16816(acc[f][j], ahf[f], bp);
                    }
            }
        }
        __syncthreads();     // stage consumed; next iter's load may overwrite the other stage
    }

    // epilogue: bias + relu + rowwise L2 norm (proven), direct bf16 hi/lo store
    const int lq = lane >> 2, lr = lane & 3;
    float ssq_p[2][2] = {{0.f, 0.f}, {0.f, 0.f}};
#pragma unroll
    for (int f = 0; f < 2; f++)
#pragma unroll
        for (int j = 0; j < NFRAG; j++) {
            float bv0 = __ldg(&bias[nc + j * 8 + 2 * lr]);
            float bv1 = __ldg(&bias[nc + j * 8 + 2 * lr + 1]);
            float v0 = fmaxf(acc[f][j][0] + bv0, 0.f);
            float v1 = fmaxf(acc[f][j][1] + bv1, 0.f);
            float v2 = fmaxf(acc[f][j][2] + bv0, 0.f);
            float v3 = fmaxf(acc[f][j][3] + bv1, 0.f);
            acc[f][j][0] = v0; acc[f][j][1] = v1; acc[f][j][2] = v2; acc[f][j][3] = v3;
            ssq_p[f][0] += v0 * v0 + v1 * v1;
            ssq_p[f][1] += v2 * v2 + v3 * v3;
        }
#pragma unroll
    for (int f = 0; f < 2; f++)
#pragma unroll
        for (int h = 0; h < 2; h++) {
            float v = ssq_p[f][h];
            v += __shfl_xor_sync(0xffffffffu, v, 1);
            v += __shfl_xor_sync(0xffffffffu, v, 2);
            if (lr == 0)
                atomicAdd((float*)(sm + C_SQ + (mr + f * 16 + h * 8 + lq) * 4), v);
        }
    __syncthreads();

    __nv_bfloat16* OH = isq ? g_Qh2 : g_Dh2;
    __nv_bfloat16* OL = isq ? g_Ql2 : g_Dl2;
#pragma unroll
    for (int f = 0; f < 2; f++)
#pragma unroll
        for (int h = 0; h < 2; h++) {
            int r = mr + f * 16 + h * 8 + lq;
            float inv = 1.f / (sqrtf(*(float*)(sm + C_SQ + r * 4)) + 1e-13f);
            bool valid;
            size_t orow;
            if (isq) {
                int pos = r & 31;
                valid = pos < NQ;
                orow = (size_t)(b0 + (r >> 5)) * 32 + pos;
            } else {
                valid = true;
                orow = (size_t)b0 * ND + m0 + r;
            }
            if (!valid) continue;
            size_t ob = orow * 384 + g * 128;
#pragma unroll
            for (int j = 0; j < NFRAG; j++) {
                float v0 = acc[f][j][h * 2 + 0] * inv;
                float v1 = acc[f][j][h * 2 + 1] * inv;
                __nv_bfloat16 h0 = __float2bfloat16(v0);
                __nv_bfloat16 h1 = __float2bfloat16(v1);
                __nv_bfloat16 l0 = __float2bfloat16(v0 - __bfloat162float(h0));
                __nv_bfloat16 l1 = __float2bfloat16(v1 - __bfloat162float(h1));
                __nv_bfloat162 ph; ph.x = h0; ph.y = h1;
                __nv_bfloat162 pl; pl.x = l0; pl.y = l1;
                size_t o = ob + nc + j * 8 + 2 * lr;
                *(__nv_bfloat162*)&OH[o] = ph;
                *(__nv_bfloat162*)&OL[o] = pl;
            }
        }
}

__global__ __launch_bounds__(256) void zero_pk()
{
    int i = blockIdx.x * 256 + threadIdx.x;
    if (i < NB * 9 * 30 * 11) g_pk[i] = 0.f;
}

// ---------------- pool: proven round-7 kernel (unchanged) ----------------
#define PM_AH 0
#define PM_AL 4608
#define PM_BH 9216
#define PM_BL 27648
#define PM_TOT 46080

__global__ __launch_bounds__(256) void poolmma(const float* __restrict__ qmask,
                                               const float* __restrict__ dmask)
{
    extern __shared__ char sm[];
    const uint32_t sbase = smem_u32(sm);

    const int tid  = threadIdx.x;
    const int wid  = tid >> 5;
    const int lane = tid & 31;
    const int nc = wid * 16;

    const int b    = blockIdx.x;
    const int pair = blockIdx.y;
    const int z    = blockIdx.z;
    const int gi = pair / 3;
    const int gt = pair - gi * 3;

    const int lg = lane >> 3, l7 = lane & 7;
    const uint32_t a_off = (((lg & 1) * 8 + l7) * 72 + ((lg >> 1) * 8)) * 2;
    const uint32_t b_off = ((nc + (lg >> 1) * 8 + l7) * 72 + ((lg & 1) * 8)) * 2;

    float acc[2][2][4];
#pragma unroll
    for (int f = 0; f < 2; f++)
#pragma unroll
        for (int j = 0; j < 2; j++)
#pragma unroll
            for (int t = 0; t < 4; t++) acc[f][j][t] = 0.f;

    for (int cc = 0; cc < 2; cc++) {
        const int e0 = cc * 64;
        const __nv_bfloat16* ah = g_Qh2 + ((size_t)b * 32) * 384 + gi * 128 + e0;
        const __nv_bfloat16* al = g_Ql2 + ((size_t)b * 32) * 384 + gi * 128 + e0;
        const __nv_bfloat16* bh = g_Dh2 + ((size_t)(b * ND + z * 128)) * 384 + gt * 128 + e0;
        const __nv_bfloat16* bl = g_Dl2 + ((size_t)(b * ND + z * 128)) * 384 + gt * 128 + e0;

        __syncthreads();
        {
            int r = tid >> 3, c = tid & 7;
            *(uint4*)(sm + PM_AH + r * 144 + c * 16) = *(const uint4*)(ah + (size_t)r * 384 + c * 8);
            *(uint4*)(sm + PM_AL + r * 144 + c * 16) = *(const uint4*)(al + (size_t)r * 384 + c * 8);
        }
#pragma unroll
        for (int u = tid; u < 1024; u += 256) {
            int r = u >> 3, c = u & 7;
            *(uint4*)(sm + PM_BH + r * 144 + c * 16) = *(const uint4*)(bh + (size_t)r * 384 + c * 8);
            *(uint4*)(sm + PM_BL + r * 144 + c * 16) = *(const uint4*)(bl + (size_t)r * 384 + c * 8);
        }
        __syncthreads();

#pragma unroll
        for (int ks = 0; ks < 4; ks++) {
            uint32_t ahf[2][4], alf[2][4], bhf[4], blf[4];
            ldsm4(ahf[0], sbase + PM_AH + a_off + ks * 32);
            ldsm4(ahf[1], sbase + PM_AH + a_off + 16 * 144 + ks * 32);
            ldsm4(alf[0], sbase + PM_AL + a_off + ks * 32);
            ldsm4(alf[1], sbase + PM_AL + a_off + 16 * 144 + ks * 32);
            ldsm4(bhf, sbase + PM_BH + b_off + ks * 32);
            ldsm4(blf, sbase + PM_BL + b_off + ks * 32);
#pragma unroll
            for (int f = 0; f < 2; f++)
#pragma unroll
                for (int j = 0; j < 2; j++) {
                    mma16816(acc[f][j], ahf[f], &bhf[j * 2]);
                    mma16816(acc[f][j], ahf[f], &blf[j * 2]);
                    mma16816(acc[f][j], alf[f], &bhf[j * 2]);
                }
        }
    }

    const int lq = lane >> 2, lr = lane & 3;
    const float U1 = 0.13533528323661270f;   // e^-2
    const float U2 = 0.018315638888734179f;  // e^-4

    float qacc[4][11];
#pragma unroll
    for (int s = 0; s < 4; s++)
#pragma unroll
        for (int k = 0; k < 11; k++) qacc[s][k] = 0.f;

#pragma unroll
    for (int f = 0; f < 2; f++)
#pragma unroll
        for (int h = 0; h < 2; h++) {
            int row = f * 16 + h * 8 + lq;
            float qmv = (row < NQ) ? __ldg(&qmask[b * NQ + row]) : 0.f;
            int slot = f * 2 + h;
#pragma unroll
            for (int j = 0; j < 2; j++)
#pragma unroll
                for (int e = 0; e < 2; e++) {
                    int col = z * 128 + nc + j * 8 + 2 * lr + e;
                    float m = qmv * __ldg(&dmask[b * ND + col]);
                    float c = acc[f][j][h * 2 + e] * m;
                    float x = c - 0.9f;
                    float e1 = __expf(-50.f * x * x) * m;
                    float t  = __expf(-20.f * x);
                    float t0 = c - 1.0f;
                    qacc[slot][0] += __expf(-500000.f * t0 * t0) * m;
                    float v = e1;
                    qacc[slot][1] += v;
                    float r = t * U1;
#pragma unroll
                    for (int kk = 2; kk < 11; kk++) {
                        v *= r;
                        qacc[slot][kk] += v;
                        r *= U2;
                    }
                }
        }

#pragma unroll
    for (int s = 0; s < 4; s++)
#pragma unroll
        for (int k = 0; k < 11; k++) {
            float v = qacc[s][k];
            v += __shfl_xor_sync(0xffffffffu, v, 1);
            v += __shfl_xor_sync(0xffffffffu, v, 2);
            qacc[s][k] = v;
        }
    if (lr == 0) {
#pragma unroll
        for (int s = 0; s < 4; s++) {
            int row = (s >> 1) * 16 + (s & 1) * 8 + lq;
            if (row < NQ) {
                float* dst = &g_pk[(((size_t)(b * 9 + pair)) * 30 + row) * 11];
#pragma unroll
                for (int k = 0; k < 11; k++) atomicAdd(&dst[k], qacc[s][k]);
            }
        }
    }
}

// ---------------- finish ----------------
__global__ __launch_bounds__(352) void finish_kernel(const float* __restrict__ qmask)
{
    __shared__ float t[330];
    const int b = blockIdx.x, pair = blockIdx.y, tid = threadIdx.x;
    if (tid < 330) {
        int row = tid / 11;
        float pk = fmaxf(g_pk[(((size_t)(b * 9 + pair)) * 30 + row) * 11 + tid % 11], 1e-10f);
        t[tid] = __logf(pk) * 0.01f * __ldg(&qmask[b * NQ + row]);
    }
    __syncthreads();
    if (tid < 11) {
        float s = 0.f;
#pragma unroll
        for (int q = 0; q < NQ; q++) s += t[q * 11 + tid];
        g_feat[b * 99 + pair * 11 + tid] = s;
    }
}

__global__ void final_kernel(const float* __restrict__ dw, float* __restrict__ out)
{
    int b = threadIdx.x;
    if (b < NB) {
        float s = 0.f;
#pragma unroll
        for (int j = 0; j < 99; j++) s += g_feat[b * 99 + j] * dw[j];
        out[b] = s;
    }
}

// ---------------- launch ----------------
extern "C" void kernel_launch(void* const* d_in, const int* in_sizes, int n_in,
                              void* d_out, int out_size)
{
    const float* qe    = (const float*)d_in[0];
    const float* de    = (const float*)d_in[1];
    const float* qmask = (const float*)d_in[2];
    const float* dmask = (const float*)d_in[3];
    const float* w1    = (const float*)d_in[4];
    const float* b1    = (const float*)d_in[5];
    const float* w2    = (const float*)d_in[6];
    const float* b2    = (const float*)d_in[7];
    const float* w3    = (const float*)d_in[8];
    const float* b3    = (const float*)d_in[9];
    const float* dw    = (const float*)d_in[10];
    float* out = (float*)d_out;

    __nv_bfloat16 *xqh, *xql, *xdh, *xdl;
    cudaGetSymbolAddress((void**)&xqh, g_Xqh);
    cudaGetSymbolAddress((void**)&xql, g_Xql);
    cudaGetSymbolAddress((void**)&xdh, g_Xdh);
    cudaGetSymbolAddress((void**)&xdl, g_Xdl);

    prep_w<<<(245760 + 255) / 256, 256>>>(w1, w2, w3);
    prep_x<XQROWS, NQ><<<(NB * XQROWS * (KP / 4) + 255) / 256, 256>>>(qe, xqh, xql);
    prep_x<XDROWS, ND><<<(NB * XDROWS * (KP / 4) + 255) / 256, 256>>>(de, xdh, xdl);

    cudaFuncSetAttribute(convmma, cudaFuncAttributeMaxDynamicSharedMemorySize, C_TOT);
    convmma<<<864, 256, C_TOT>>>(b1, b2, b3);

    zero_pk<<<(NB * 9 * 30 * 11 + 255) / 256, 256>>>();

    cudaFuncSetAttribute(poolmma, cudaFuncAttributeMaxDynamicSharedMemorySize, PM_TOT);
    poolmma<<<dim3(NB, 9, 2), 256, PM_TOT>>>(qmask, dmask);

    finish_kernel<<<dim3(NB, 9), 352>>>(qmask);
    final_kernel<<<1, 128>>>(dw, out);
}